// round 2
// baseline (speedup 1.0000x reference)
#include <cuda_runtime.h>
#include <math.h>
#include <stdint.h>

#define N_NODES   50000
#define N_EDGES   800000
#define HID       256
#define NUM_GRAPHS 512
#define LEAKY     0.01f
#define LN_EPS    1e-5f

// ---------------- device scratch (no allocations allowed) ----------------
__device__ int   g_is64;                      // 1 if indices are int64
__device__ int   g_deg[N_NODES];              // in-degree incl self loop
__device__ float g_dinv[N_NODES];             // rsqrt(deg)
__device__ int   g_rowptr[N_NODES + 1];       // CSR by dst
__device__ int   g_cursor[N_NODES];
__device__ int   g_csr_src[N_EDGES];
__device__ float g_hA[(size_t)N_NODES * HID]; // ping
__device__ float g_hB[(size_t)N_NODES * HID]; // pong

__device__ __forceinline__ int load_idx(const void* p, long long i, int is64) {
    return is64 ? (int)((const long long*)p)[i] : ((const int*)p)[i];
}

// ---------------- dtype detection (int32 vs int64 indices) ----------------
// If the buffer holds int64 values in [0, 50000), every odd 32-bit word of the
// first 1024 elements is 0. For int32 data those words are random node ids.
__global__ void k_detect(const void* edge) {
    __shared__ int any;
    if (threadIdx.x == 0) any = 0;
    __syncthreads();
    const int* w = (const int*)edge;
    int local = 0;
    for (int i = threadIdx.x; i < 1024; i += blockDim.x)
        if (w[2 * i + 1] != 0) local = 1;
    if (local) atomicOr(&any, 1);
    __syncthreads();
    if (threadIdx.x == 0) g_is64 = (any == 0) ? 1 : 0;
}

// ---------------- degree / CSR build ----------------
__global__ void k_init_deg() {
    int i = blockIdx.x * blockDim.x + threadIdx.x;
    if (i < N_NODES) g_deg[i] = 1;   // self loop
}

__global__ void k_count(const void* edge) {
    int e = blockIdx.x * blockDim.x + threadIdx.x;
    if (e >= N_EDGES) return;
    int is64 = g_is64;
    int d = load_idx(edge, (long long)N_EDGES + e, is64);
    atomicAdd(&g_deg[d], 1);
}

__global__ void k_dinv() {
    int i = blockIdx.x * blockDim.x + threadIdx.x;
    if (i < N_NODES) g_dinv[i] = rsqrtf((float)g_deg[i]);
}

// single-block exclusive scan of (deg-1) -> rowptr, cursor
__global__ void k_scan() {
    __shared__ int s[1024];
    __shared__ int carry;
    if (threadIdx.x == 0) carry = 0;
    __syncthreads();
    const int n = N_NODES;
    int nchunks = (n + 1023) / 1024;
    for (int c = 0; c < nchunks; c++) {
        int i = c * 1024 + threadIdx.x;
        int v = (i < n) ? (g_deg[i] - 1) : 0;
        s[threadIdx.x] = v;
        __syncthreads();
        for (int off = 1; off < 1024; off <<= 1) {
            int t = (threadIdx.x >= off) ? s[threadIdx.x - off] : 0;
            __syncthreads();
            if (threadIdx.x >= off) s[threadIdx.x] += t;
            __syncthreads();
        }
        int incl = s[threadIdx.x];
        int excl = carry + incl - v;
        if (i < n) { g_rowptr[i] = excl; g_cursor[i] = excl; }
        __syncthreads();
        if (threadIdx.x == 0) carry += s[1023];
        __syncthreads();
    }
    if (threadIdx.x == 0) g_rowptr[n] = carry;
}

__global__ void k_scatter(const void* edge) {
    int e = blockIdx.x * blockDim.x + threadIdx.x;
    if (e >= N_EDGES) return;
    int is64 = g_is64;
    int srce = load_idx(edge, e, is64);
    int dste = load_idx(edge, (long long)N_EDGES + e, is64);
    int pos = atomicAdd(&g_cursor[dste], 1);
    g_csr_src[pos] = srce;
}

// ---------------- GEMM: C[M,256] = A[M,256] @ W[256,256] ----------------
#define BM 64
#define BN 64
#define BK 32

__global__ void k_gemm(const float* __restrict__ A, const float* __restrict__ W,
                       float* __restrict__ C, int M) {
    __shared__ float As[BK][BM + 4];  // transposed, padded (16B-aligned rows)
    __shared__ float Bs[BK][BN];

    int tid = threadIdx.x;
    int tx = tid & 15;        // 0..15 -> N
    int ty = tid >> 4;        // 0..15 -> M
    int m0 = blockIdx.x * BM;
    int n0 = blockIdx.y * BN;

    float acc[4][4];
#pragma unroll
    for (int i = 0; i < 4; i++)
#pragma unroll
        for (int j = 0; j < 4; j++) acc[i][j] = 0.f;

    for (int k0 = 0; k0 < 256; k0 += BK) {
        // load A tile (transpose to As[k][m])
#pragma unroll
        for (int r = 0; r < 2; r++) {
            int f4 = tid + r * 256;          // 0..511
            int ml = f4 >> 3;                // 0..63
            int kq = f4 & 7;                 // 0..7
            int m = m0 + ml;
            float4 v = make_float4(0.f, 0.f, 0.f, 0.f);
            if (m < M) v = *(const float4*)&A[(size_t)m * 256 + k0 + kq * 4];
            As[kq * 4 + 0][ml] = v.x;
            As[kq * 4 + 1][ml] = v.y;
            As[kq * 4 + 2][ml] = v.z;
            As[kq * 4 + 3][ml] = v.w;
        }
        // load W tile
#pragma unroll
        for (int r = 0; r < 2; r++) {
            int f4 = tid + r * 256;
            int kl = f4 >> 4;                // 0..31
            int nq = f4 & 15;                // 0..15
            *(float4*)&Bs[kl][nq * 4] =
                *(const float4*)&W[(size_t)(k0 + kl) * 256 + n0 + nq * 4];
        }
        __syncthreads();

#pragma unroll
        for (int kk = 0; kk < BK; kk++) {
            float4 av = *(const float4*)&As[kk][ty * 4];
            float4 bv = *(const float4*)&Bs[kk][tx * 4];
            float a[4] = {av.x, av.y, av.z, av.w};
            float b[4] = {bv.x, bv.y, bv.z, bv.w};
#pragma unroll
            for (int i = 0; i < 4; i++)
#pragma unroll
                for (int j = 0; j < 4; j++) acc[i][j] += a[i] * b[j];
        }
        __syncthreads();
    }

#pragma unroll
    for (int i = 0; i < 4; i++) {
        int m = m0 + ty * 4 + i;
        if (m < M) {
            float4 v = make_float4(acc[i][0], acc[i][1], acc[i][2], acc[i][3]);
            *(float4*)&C[(size_t)m * 256 + n0 + tx * 4] = v;
        }
    }
}

// ---------------- fused aggregate + bias + LayerNorm + LeakyReLU ----------
// one warp per node; lane owns features [8*lane, 8*lane+8)
__global__ void k_agg_ln(const float* __restrict__ h, float* __restrict__ out,
                         const float* __restrict__ bias,
                         const float* __restrict__ lnw,
                         const float* __restrict__ lnb) {
    int warp = (blockIdx.x * blockDim.x + threadIdx.x) >> 5;
    int lane = threadIdx.x & 31;
    if (warp >= N_NODES) return;
    int node = warp;
    int c0 = lane * 2;   // float4 index within row

    float di = g_dinv[node];
    const float4* selfrow = (const float4*)(h + (size_t)node * HID);
    float4 a0 = selfrow[c0];
    float4 a1 = selfrow[c0 + 1];
    float ws = di * di;
    a0.x *= ws; a0.y *= ws; a0.z *= ws; a0.w *= ws;
    a1.x *= ws; a1.y *= ws; a1.z *= ws; a1.w *= ws;

    int beg = g_rowptr[node];
    int end = g_rowptr[node + 1];
#pragma unroll 4
    for (int e = beg; e < end; e++) {
        int s = g_csr_src[e];
        float wv = g_dinv[s] * di;
        const float4* r = (const float4*)(h + (size_t)s * HID);
        float4 r0 = r[c0];
        float4 r1 = r[c0 + 1];
        a0.x += r0.x * wv; a0.y += r0.y * wv; a0.z += r0.z * wv; a0.w += r0.w * wv;
        a1.x += r1.x * wv; a1.y += r1.y * wv; a1.z += r1.z * wv; a1.w += r1.w * wv;
    }

    // + bias
    float4 b0 = ((const float4*)bias)[c0];
    float4 b1 = ((const float4*)bias)[c0 + 1];
    a0.x += b0.x; a0.y += b0.y; a0.z += b0.z; a0.w += b0.w;
    a1.x += b1.x; a1.y += b1.y; a1.z += b1.z; a1.w += b1.w;

    // LayerNorm over 256 features
    float sum = a0.x + a0.y + a0.z + a0.w + a1.x + a1.y + a1.z + a1.w;
#pragma unroll
    for (int off = 16; off > 0; off >>= 1)
        sum += __shfl_xor_sync(0xffffffff, sum, off);
    float mu = sum * (1.0f / HID);

    float d0x = a0.x - mu, d0y = a0.y - mu, d0z = a0.z - mu, d0w = a0.w - mu;
    float d1x = a1.x - mu, d1y = a1.y - mu, d1z = a1.z - mu, d1w = a1.w - mu;
    float sq = d0x * d0x + d0y * d0y + d0z * d0z + d0w * d0w +
               d1x * d1x + d1y * d1y + d1z * d1z + d1w * d1w;
#pragma unroll
    for (int off = 16; off > 0; off >>= 1)
        sq += __shfl_xor_sync(0xffffffff, sq, off);
    float inv = rsqrtf(sq * (1.0f / HID) + LN_EPS);

    float4 w0 = ((const float4*)lnw)[c0];
    float4 w1 = ((const float4*)lnw)[c0 + 1];
    float4 lb0 = ((const float4*)lnb)[c0];
    float4 lb1 = ((const float4*)lnb)[c0 + 1];

    float v[8];
    v[0] = d0x * inv * w0.x + lb0.x;
    v[1] = d0y * inv * w0.y + lb0.y;
    v[2] = d0z * inv * w0.z + lb0.z;
    v[3] = d0w * inv * w0.w + lb0.w;
    v[4] = d1x * inv * w1.x + lb1.x;
    v[5] = d1y * inv * w1.y + lb1.y;
    v[6] = d1z * inv * w1.z + lb1.z;
    v[7] = d1w * inv * w1.w + lb1.w;
#pragma unroll
    for (int i = 0; i < 8; i++) v[i] = (v[i] >= 0.f) ? v[i] : LEAKY * v[i];

    float4* orow = (float4*)(out + (size_t)node * HID);
    orow[c0]     = make_float4(v[0], v[1], v[2], v[3]);
    orow[c0 + 1] = make_float4(v[4], v[5], v[6], v[7]);
}

// ---------------- per-graph mean pool (batch is sorted) ----------------
__global__ void k_pool(const float* __restrict__ h, const void* batch,
                       float* __restrict__ out) {
    int g = blockIdx.x;
    int is64 = g_is64;

    int lo = 0, hi = N_NODES;
    while (lo < hi) {
        int mid = (lo + hi) >> 1;
        if (load_idx(batch, mid, is64) < g) lo = mid + 1; else hi = mid;
    }
    int start = lo;
    hi = N_NODES;
    while (lo < hi) {
        int mid = (lo + hi) >> 1;
        if (load_idx(batch, mid, is64) < g + 1) lo = mid + 1; else hi = mid;
    }
    int end = lo;

    int t = threadIdx.x;
    float acc = 0.f;
    for (int i = start; i < end; i++)
        acc += h[(size_t)i * HID + t];
    float cnt = (float)(end - start);
    out[(size_t)g * HID + t] = acc / fmaxf(cnt, 1.f);
}

// ---------------- launch ----------------
extern "C" void kernel_launch(void* const* d_in, const int* in_sizes, int n_in,
                              void* d_out, int out_size) {
    const float* x    = (const float*)d_in[0];
    const void*  edge = d_in[1];
    const void*  batch= d_in[2];
    const float* W1   = (const float*)d_in[3];
    const float* b1   = (const float*)d_in[4];
    const float* ln1w = (const float*)d_in[5];
    const float* ln1b = (const float*)d_in[6];
    const float* W2   = (const float*)d_in[7];
    const float* b2   = (const float*)d_in[8];
    const float* ln2w = (const float*)d_in[9];
    const float* ln2b = (const float*)d_in[10];
    float* out = (float*)d_out;

    float *hA = nullptr, *hB = nullptr;
    cudaGetSymbolAddress((void**)&hA, g_hA);
    cudaGetSymbolAddress((void**)&hB, g_hB);

    const int TB = 256;
    int gN = (N_NODES + TB - 1) / TB;     // 196
    int gE = (N_EDGES + TB - 1) / TB;     // 3125

    k_detect<<<1, 256>>>(edge);
    k_init_deg<<<gN, TB>>>();
    k_count<<<gE, TB>>>(edge);
    k_dinv<<<gN, TB>>>();
    k_scan<<<1, 1024>>>();
    k_scatter<<<gE, TB>>>(edge);

    dim3 gemmGrid((N_NODES + BM - 1) / BM, 256 / BN);  // (782, 4)
    int aggBlocks = (N_NODES * 32 + TB - 1) / TB;      // 6250

    // layer 1
    k_gemm<<<gemmGrid, TB>>>(x, W1, hA, N_NODES);
    k_agg_ln<<<aggBlocks, TB>>>(hA, hB, b1, ln1w, ln1b);

    // layer 2
    k_gemm<<<gemmGrid, TB>>>(hB, W2, hA, N_NODES);
    k_agg_ln<<<aggBlocks, TB>>>(hA, hB, b2, ln2w, ln2b);

    // pool
    k_pool<<<NUM_GRAPHS, HID>>>(hB, batch, out);
}

// round 3
// speedup vs baseline: 1.1324x; 1.1324x over previous
#include <cuda_runtime.h>
#include <math.h>
#include <stdint.h>

#define N_NODES   50000
#define N_EDGES   800000
#define HID       256
#define NUM_GRAPHS 512
#define LEAKY     0.01f
#define LN_EPS    1e-5f

// ---------------- device scratch ----------------
__device__ int   g_is64;
__device__ int   g_deg[N_NODES];
__device__ float g_dinv[N_NODES];
__device__ int   g_rowptr[N_NODES + 1];
__device__ int   g_cursor[N_NODES];
__device__ int   g_csr_src[N_EDGES];
__device__ float g_hA[(size_t)N_NODES * HID];
__device__ float g_hB[(size_t)N_NODES * HID];

__device__ __forceinline__ int load_idx(const void* p, long long i, int is64) {
    return is64 ? (int)((const long long*)p)[i] : ((const int*)p)[i];
}

// ---------------- fused: init deg + dtype detect ----------------
__global__ void k_detect_init(const void* edge, int gN) {
    if (blockIdx.x < gN) {
        int i = blockIdx.x * blockDim.x + threadIdx.x;
        if (i < N_NODES) g_deg[i] = 1;   // self loop
        return;
    }
    // last block: detect int64 vs int32 (odd 32-bit words all zero => int64)
    __shared__ int any;
    if (threadIdx.x == 0) any = 0;
    __syncthreads();
    const int* w = (const int*)edge;
    int local = 0;
    for (int i = threadIdx.x; i < 1024; i += blockDim.x)
        if (w[2 * i + 1] != 0) local = 1;
    if (local) atomicOr(&any, 1);
    __syncthreads();
    if (threadIdx.x == 0) g_is64 = (any == 0) ? 1 : 0;
}

__global__ void k_count(const void* edge) {
    int e = blockIdx.x * blockDim.x + threadIdx.x;
    if (e >= N_EDGES) return;
    int is64 = g_is64;
    int d = load_idx(edge, (long long)N_EDGES + e, is64);
    atomicAdd(&g_deg[d], 1);
}

// ---------------- single-block warp-shuffle scan (+ fused dinv) ----------
__global__ void k_scan() {
    __shared__ int wsum[32];
    __shared__ int carry_s;
    if (threadIdx.x == 0) carry_s = 0;
    __syncthreads();

    const int n = N_NODES;
    int tid  = threadIdx.x;
    int lane = tid & 31;
    int wid  = tid >> 5;
    int nchunks = (n + 1023) / 1024;

    for (int c = 0; c < nchunks; c++) {
        int i = c * 1024 + tid;
        int deg = (i < n) ? g_deg[i] : 1;
        int v = (i < n) ? (deg - 1) : 0;

        // warp inclusive scan
        int x = v;
#pragma unroll
        for (int off = 1; off < 32; off <<= 1) {
            int t = __shfl_up_sync(0xffffffff, x, off);
            if (lane >= off) x += t;
        }
        if (lane == 31) wsum[wid] = x;
        __syncthreads();
        if (wid == 0) {
            int y = wsum[lane];
#pragma unroll
            for (int off = 1; off < 32; off <<= 1) {
                int t = __shfl_up_sync(0xffffffff, y, off);
                if (lane >= off) y += t;
            }
            wsum[lane] = y;
        }
        __syncthreads();

        int carry = carry_s;
        int excl = carry + (wid ? wsum[wid - 1] : 0) + x - v;
        if (i < n) {
            g_rowptr[i] = excl;
            g_cursor[i] = excl;
            g_dinv[i]   = rsqrtf((float)deg);
        }
        __syncthreads();
        if (tid == 0) carry_s = carry + wsum[31];
        __syncthreads();
    }
    if (tid == 0) g_rowptr[n] = carry_s;
}

__global__ void k_scatter(const void* edge) {
    int e = blockIdx.x * blockDim.x + threadIdx.x;
    if (e >= N_EDGES) return;
    int is64 = g_is64;
    int srce = load_idx(edge, e, is64);
    int dste = load_idx(edge, (long long)N_EDGES + e, is64);
    int pos = atomicAdd(&g_cursor[dste], 1);
    g_csr_src[pos] = srce;
}

// ---------------- GEMM: C[M,256] = A[M,256] @ W[256,256] ----------------
// 128x128 tile, BK=16, 256 threads, 8x8 per thread, double-buffered smem.
#define BM 128
#define BN 128
#define BK 16

__global__ void __launch_bounds__(256)
k_gemm(const float* __restrict__ A, const float* __restrict__ W,
       float* __restrict__ C, int M) {
    __shared__ float As[2][BK][BM + 4];
    __shared__ float Bs[2][BK][BN];

    int tid = threadIdx.x;
    int tx = tid & 15;         // 0..15
    int ty = tid >> 4;         // 0..15
    int m0 = blockIdx.x * BM;
    int n0 = blockIdx.y * BN;

    // global load mapping
    int arow0 = tid >> 2;          // 0..63  (second half +64)
    int ac4   = tid & 3;           // k-quad within BK=16
    int brow0 = tid >> 5;          // 0..7   (second half +8)
    int bc4   = tid & 31;          // n-quad

    float acc[8][8];
#pragma unroll
    for (int i = 0; i < 8; i++)
#pragma unroll
        for (int j = 0; j < 8; j++) acc[i][j] = 0.f;

    // ---- load stage 0 ----
    float4 pa0, pa1, pb0, pb1;
    {
        int m = m0 + arow0;
        pa0 = (m < M) ? *(const float4*)&A[(size_t)m * 256 + ac4 * 4]
                      : make_float4(0.f, 0.f, 0.f, 0.f);
        m = m0 + arow0 + 64;
        pa1 = (m < M) ? *(const float4*)&A[(size_t)m * 256 + ac4 * 4]
                      : make_float4(0.f, 0.f, 0.f, 0.f);
        pb0 = *(const float4*)&W[(size_t)brow0 * 256 + n0 + bc4 * 4];
        pb1 = *(const float4*)&W[(size_t)(brow0 + 8) * 256 + n0 + bc4 * 4];
    }
    {
        As[0][ac4 * 4 + 0][arow0] = pa0.x;
        As[0][ac4 * 4 + 1][arow0] = pa0.y;
        As[0][ac4 * 4 + 2][arow0] = pa0.z;
        As[0][ac4 * 4 + 3][arow0] = pa0.w;
        As[0][ac4 * 4 + 0][arow0 + 64] = pa1.x;
        As[0][ac4 * 4 + 1][arow0 + 64] = pa1.y;
        As[0][ac4 * 4 + 2][arow0 + 64] = pa1.z;
        As[0][ac4 * 4 + 3][arow0 + 64] = pa1.w;
        *(float4*)&Bs[0][brow0][bc4 * 4]     = pb0;
        *(float4*)&Bs[0][brow0 + 8][bc4 * 4] = pb1;
    }
    __syncthreads();

    int buf = 0;
    for (int k0 = 0; k0 < 256; k0 += BK) {
        bool has_next = (k0 + BK) < 256;
        if (has_next) {
            int kb = k0 + BK;
            int m = m0 + arow0;
            pa0 = (m < M) ? *(const float4*)&A[(size_t)m * 256 + kb + ac4 * 4]
                          : make_float4(0.f, 0.f, 0.f, 0.f);
            m = m0 + arow0 + 64;
            pa1 = (m < M) ? *(const float4*)&A[(size_t)m * 256 + kb + ac4 * 4]
                          : make_float4(0.f, 0.f, 0.f, 0.f);
            pb0 = *(const float4*)&W[(size_t)(kb + brow0) * 256 + n0 + bc4 * 4];
            pb1 = *(const float4*)&W[(size_t)(kb + brow0 + 8) * 256 + n0 + bc4 * 4];
        }

#pragma unroll
        for (int kk = 0; kk < BK; kk++) {
            float4 a0 = *(const float4*)&As[buf][kk][ty * 4];
            float4 a1 = *(const float4*)&As[buf][kk][64 + ty * 4];
            float4 b0 = *(const float4*)&Bs[buf][kk][tx * 4];
            float4 b1 = *(const float4*)&Bs[buf][kk][64 + tx * 4];
            float a[8] = {a0.x, a0.y, a0.z, a0.w, a1.x, a1.y, a1.z, a1.w};
            float b[8] = {b0.x, b0.y, b0.z, b0.w, b1.x, b1.y, b1.z, b1.w};
#pragma unroll
            for (int i = 0; i < 8; i++)
#pragma unroll
                for (int j = 0; j < 8; j++) acc[i][j] += a[i] * b[j];
        }

        if (has_next) {
            int nb = buf ^ 1;
            As[nb][ac4 * 4 + 0][arow0] = pa0.x;
            As[nb][ac4 * 4 + 1][arow0] = pa0.y;
            As[nb][ac4 * 4 + 2][arow0] = pa0.z;
            As[nb][ac4 * 4 + 3][arow0] = pa0.w;
            As[nb][ac4 * 4 + 0][arow0 + 64] = pa1.x;
            As[nb][ac4 * 4 + 1][arow0 + 64] = pa1.y;
            As[nb][ac4 * 4 + 2][arow0 + 64] = pa1.z;
            As[nb][ac4 * 4 + 3][arow0 + 64] = pa1.w;
            *(float4*)&Bs[nb][brow0][bc4 * 4]     = pb0;
            *(float4*)&Bs[nb][brow0 + 8][bc4 * 4] = pb1;
            __syncthreads();
            buf = nb;
        }
    }

    // epilogue: rows ty*4..+3 and 64+ty*4..+3; cols tx*4 and 64+tx*4 (float4)
#pragma unroll
    for (int i = 0; i < 8; i++) {
        int m = m0 + ((i < 4) ? (ty * 4 + i) : (64 + ty * 4 + i - 4));
        if (m < M) {
            *(float4*)&C[(size_t)m * 256 + n0 + tx * 4] =
                make_float4(acc[i][0], acc[i][1], acc[i][2], acc[i][3]);
            *(float4*)&C[(size_t)m * 256 + n0 + 64 + tx * 4] =
                make_float4(acc[i][4], acc[i][5], acc[i][6], acc[i][7]);
        }
    }
}

// ---------------- fused aggregate + bias + LayerNorm + LeakyReLU ----------
__global__ void k_agg_ln(const float* __restrict__ h, float* __restrict__ out,
                         const float* __restrict__ bias,
                         const float* __restrict__ lnw,
                         const float* __restrict__ lnb) {
    int warp = (blockIdx.x * blockDim.x + threadIdx.x) >> 5;
    int lane = threadIdx.x & 31;
    if (warp >= N_NODES) return;
    int node = warp;
    int c0 = lane * 2;

    float di = g_dinv[node];
    const float4* selfrow = (const float4*)(h + (size_t)node * HID);
    float4 a0 = selfrow[c0];
    float4 a1 = selfrow[c0 + 1];
    float ws = di * di;
    a0.x *= ws; a0.y *= ws; a0.z *= ws; a0.w *= ws;
    a1.x *= ws; a1.y *= ws; a1.z *= ws; a1.w *= ws;

    // second accumulator set for 2-way edge unroll (more LDG MLP)
    float4 c0v = make_float4(0.f, 0.f, 0.f, 0.f);
    float4 c1v = make_float4(0.f, 0.f, 0.f, 0.f);

    int beg = g_rowptr[node];
    int end = g_rowptr[node + 1];
    int e = beg;
    for (; e + 1 < end; e += 2) {
        int s1 = g_csr_src[e];
        int s2 = g_csr_src[e + 1];
        float w1 = g_dinv[s1] * di;
        float w2 = g_dinv[s2] * di;
        const float4* r1 = (const float4*)(h + (size_t)s1 * HID);
        const float4* r2 = (const float4*)(h + (size_t)s2 * HID);
        float4 x0 = r1[c0], x1 = r1[c0 + 1];
        float4 y0 = r2[c0], y1 = r2[c0 + 1];
        a0.x += x0.x * w1; a0.y += x0.y * w1; a0.z += x0.z * w1; a0.w += x0.w * w1;
        a1.x += x1.x * w1; a1.y += x1.y * w1; a1.z += x1.z * w1; a1.w += x1.w * w1;
        c0v.x += y0.x * w2; c0v.y += y0.y * w2; c0v.z += y0.z * w2; c0v.w += y0.w * w2;
        c1v.x += y1.x * w2; c1v.y += y1.y * w2; c1v.z += y1.z * w2; c1v.w += y1.w * w2;
    }
    if (e < end) {
        int s = g_csr_src[e];
        float wv = g_dinv[s] * di;
        const float4* r = (const float4*)(h + (size_t)s * HID);
        float4 x0 = r[c0], x1 = r[c0 + 1];
        a0.x += x0.x * wv; a0.y += x0.y * wv; a0.z += x0.z * wv; a0.w += x0.w * wv;
        a1.x += x1.x * wv; a1.y += x1.y * wv; a1.z += x1.z * wv; a1.w += x1.w * wv;
    }
    a0.x += c0v.x; a0.y += c0v.y; a0.z += c0v.z; a0.w += c0v.w;
    a1.x += c1v.x; a1.y += c1v.y; a1.z += c1v.z; a1.w += c1v.w;

    float4 b0 = ((const float4*)bias)[c0];
    float4 b1 = ((const float4*)bias)[c0 + 1];
    a0.x += b0.x; a0.y += b0.y; a0.z += b0.z; a0.w += b0.w;
    a1.x += b1.x; a1.y += b1.y; a1.z += b1.z; a1.w += b1.w;

    float sum = a0.x + a0.y + a0.z + a0.w + a1.x + a1.y + a1.z + a1.w;
#pragma unroll
    for (int off = 16; off > 0; off >>= 1)
        sum += __shfl_xor_sync(0xffffffff, sum, off);
    float mu = sum * (1.0f / HID);

    float d0x = a0.x - mu, d0y = a0.y - mu, d0z = a0.z - mu, d0w = a0.w - mu;
    float d1x = a1.x - mu, d1y = a1.y - mu, d1z = a1.z - mu, d1w = a1.w - mu;
    float sq = d0x * d0x + d0y * d0y + d0z * d0z + d0w * d0w +
               d1x * d1x + d1y * d1y + d1z * d1z + d1w * d1w;
#pragma unroll
    for (int off = 16; off > 0; off >>= 1)
        sq += __shfl_xor_sync(0xffffffff, sq, off);
    float inv = rsqrtf(sq * (1.0f / HID) + LN_EPS);

    float4 w0 = ((const float4*)lnw)[c0];
    float4 w1 = ((const float4*)lnw)[c0 + 1];
    float4 lb0 = ((const float4*)lnb)[c0];
    float4 lb1 = ((const float4*)lnb)[c0 + 1];

    float v[8];
    v[0] = d0x * inv * w0.x + lb0.x;
    v[1] = d0y * inv * w0.y + lb0.y;
    v[2] = d0z * inv * w0.z + lb0.z;
    v[3] = d0w * inv * w0.w + lb0.w;
    v[4] = d1x * inv * w1.x + lb1.x;
    v[5] = d1y * inv * w1.y + lb1.y;
    v[6] = d1z * inv * w1.z + lb1.z;
    v[7] = d1w * inv * w1.w + lb1.w;
#pragma unroll
    for (int i = 0; i < 8; i++) v[i] = (v[i] >= 0.f) ? v[i] : LEAKY * v[i];

    float4* orow = (float4*)(out + (size_t)node * HID);
    orow[c0]     = make_float4(v[0], v[1], v[2], v[3]);
    orow[c0 + 1] = make_float4(v[4], v[5], v[6], v[7]);
}

// ---------------- per-graph mean pool ----------------
__global__ void k_pool(const float* __restrict__ h, const void* batch,
                       float* __restrict__ out) {
    int g = blockIdx.x;
    int is64 = g_is64;

    int lo = 0, hi = N_NODES;
    while (lo < hi) {
        int mid = (lo + hi) >> 1;
        if (load_idx(batch, mid, is64) < g) lo = mid + 1; else hi = mid;
    }
    int start = lo;
    hi = N_NODES;
    while (lo < hi) {
        int mid = (lo + hi) >> 1;
        if (load_idx(batch, mid, is64) < g + 1) lo = mid + 1; else hi = mid;
    }
    int end = lo;

    int t = threadIdx.x;
    float acc = 0.f;
    for (int i = start; i < end; i++)
        acc += h[(size_t)i * HID + t];
    float cnt = (float)(end - start);
    out[(size_t)g * HID + t] = acc / fmaxf(cnt, 1.f);
}

// ---------------- launch ----------------
extern "C" void kernel_launch(void* const* d_in, const int* in_sizes, int n_in,
                              void* d_out, int out_size) {
    const float* x    = (const float*)d_in[0];
    const void*  edge = d_in[1];
    const void*  batch= d_in[2];
    const float* W1   = (const float*)d_in[3];
    const float* b1   = (const float*)d_in[4];
    const float* ln1w = (const float*)d_in[5];
    const float* ln1b = (const float*)d_in[6];
    const float* W2   = (const float*)d_in[7];
    const float* b2   = (const float*)d_in[8];
    const float* ln2w = (const float*)d_in[9];
    const float* ln2b = (const float*)d_in[10];
    float* out = (float*)d_out;

    float *hA = nullptr, *hB = nullptr;
    cudaGetSymbolAddress((void**)&hA, g_hA);
    cudaGetSymbolAddress((void**)&hB, g_hB);

    const int TB = 256;
    int gN = (N_NODES + TB - 1) / TB;     // 196
    int gE = (N_EDGES + TB - 1) / TB;     // 3125

    k_detect_init<<<gN + 1, TB>>>(edge, gN);
    k_count<<<gE, TB>>>(edge);
    k_scan<<<1, 1024>>>();
    k_scatter<<<gE, TB>>>(edge);

    dim3 gemmGrid((N_NODES + BM - 1) / BM, 256 / BN);  // (391, 2)
    int aggBlocks = (N_NODES * 32 + TB - 1) / TB;      // 6250

    k_gemm<<<gemmGrid, TB>>>(x, W1, hA, N_NODES);
    k_agg_ln<<<aggBlocks, TB>>>(hA, hB, b1, ln1w, ln1b);

    k_gemm<<<gemmGrid, TB>>>(hB, W2, hA, N_NODES);
    k_agg_ln<<<aggBlocks, TB>>>(hA, hB, b2, ln2w, ln2b);

    k_pool<<<NUM_GRAPHS, HID>>>(hB, batch, out);
}

// round 4
// speedup vs baseline: 1.7308x; 1.5284x over previous
#include <cuda_runtime.h>
#include <math.h>
#include <stdint.h>

#define N_NODES   50000
#define N_EDGES   800000
#define HID       256
#define NUM_GRAPHS 512
#define LEAKY     0.01f
#define LN_EPS    1e-5f

// ---------------- device scratch ----------------
__device__ int   g_is64;
__device__ int   g_deg[N_NODES];
__device__ float g_dinv[N_NODES];
__device__ int   g_rowptr[N_NODES + 1];
__device__ int   g_cursor[N_NODES];
__device__ int   g_csr_src[N_EDGES];
__device__ float g_hA[(size_t)N_NODES * HID];
__device__ float g_hB[(size_t)N_NODES * HID];

__device__ __forceinline__ int load_idx(const void* p, long long i, int is64) {
    return is64 ? (int)((const long long*)p)[i] : ((const int*)p)[i];
}

__device__ __forceinline__ uint32_t to_tf32(float x) {
    uint32_t r;
    asm("cvt.rna.tf32.f32 %0, %1;" : "=r"(r) : "f"(x));
    return r;
}

// ---------------- fused: init deg + dtype detect ----------------
__global__ void k_detect_init(const void* edge, int gN) {
    if (blockIdx.x < gN) {
        int i = blockIdx.x * blockDim.x + threadIdx.x;
        if (i < N_NODES) g_deg[i] = 1;
        return;
    }
    __shared__ int any;
    if (threadIdx.x == 0) any = 0;
    __syncthreads();
    const int* w = (const int*)edge;
    int local = 0;
    for (int i = threadIdx.x; i < 1024; i += blockDim.x)
        if (w[2 * i + 1] != 0) local = 1;
    if (local) atomicOr(&any, 1);
    __syncthreads();
    if (threadIdx.x == 0) g_is64 = (any == 0) ? 1 : 0;
}

__global__ void k_count(const void* edge) {
    int e = blockIdx.x * blockDim.x + threadIdx.x;
    if (e >= N_EDGES) return;
    int is64 = g_is64;
    int d = load_idx(edge, (long long)N_EDGES + e, is64);
    atomicAdd(&g_deg[d], 1);
}

// ---------------- single-block warp-shuffle scan (+ fused dinv) ----------
__global__ void k_scan() {
    __shared__ int wsum[32];
    __shared__ int carry_s;
    if (threadIdx.x == 0) carry_s = 0;
    __syncthreads();

    const int n = N_NODES;
    int tid  = threadIdx.x;
    int lane = tid & 31;
    int wid  = tid >> 5;
    int nchunks = (n + 1023) / 1024;

    for (int c = 0; c < nchunks; c++) {
        int i = c * 1024 + tid;
        int deg = (i < n) ? g_deg[i] : 1;
        int v = (i < n) ? (deg - 1) : 0;

        int x = v;
#pragma unroll
        for (int off = 1; off < 32; off <<= 1) {
            int t = __shfl_up_sync(0xffffffff, x, off);
            if (lane >= off) x += t;
        }
        if (lane == 31) wsum[wid] = x;
        __syncthreads();
        if (wid == 0) {
            int y = wsum[lane];
#pragma unroll
            for (int off = 1; off < 32; off <<= 1) {
                int t = __shfl_up_sync(0xffffffff, y, off);
                if (lane >= off) y += t;
            }
            wsum[lane] = y;
        }
        __syncthreads();

        int carry = carry_s;
        int excl = carry + (wid ? wsum[wid - 1] : 0) + x - v;
        if (i < n) {
            g_rowptr[i] = excl;
            g_cursor[i] = excl;
            g_dinv[i]   = rsqrtf((float)deg);
        }
        __syncthreads();
        if (tid == 0) carry_s = carry + wsum[31];
        __syncthreads();
    }
    if (tid == 0) g_rowptr[n] = carry_s;
}

__global__ void k_scatter(const void* edge) {
    int e = blockIdx.x * blockDim.x + threadIdx.x;
    if (e >= N_EDGES) return;
    int is64 = g_is64;
    int srce = load_idx(edge, e, is64);
    int dste = load_idx(edge, (long long)N_EDGES + e, is64);
    int pos = atomicAdd(&g_cursor[dste], 1);
    g_csr_src[pos] = srce;
}

// ---------------- tf32 tensor-core GEMM: C[M,256] = A @ W ----------------
// 128x128 tile, BK=16, 256 thr = 8 warps (2x4), warp tile 64x32,
// m16n8k8 tf32 mma, double-buffered smem, RNA rounding at staging.
#define BM 128
#define BN 128
#define BK 16
#define ASTRIDE (BM + 8)   // 136: conflict-free fragment loads
#define BSTRIDE (BN + 8)

__device__ __forceinline__ void mma_tf32(float* c, const uint32_t* a, const uint32_t* b) {
    asm volatile(
        "mma.sync.aligned.m16n8k8.row.col.f32.tf32.tf32.f32 "
        "{%0,%1,%2,%3}, {%4,%5,%6,%7}, {%8,%9}, {%0,%1,%2,%3};"
        : "+f"(c[0]), "+f"(c[1]), "+f"(c[2]), "+f"(c[3])
        : "r"(a[0]), "r"(a[1]), "r"(a[2]), "r"(a[3]), "r"(b[0]), "r"(b[1]));
}

__global__ void __launch_bounds__(256)
k_gemm(const float* __restrict__ A, const float* __restrict__ W,
       float* __restrict__ C, int M) {
    __shared__ float As[2][BK][ASTRIDE];
    __shared__ float Bs[2][BK][BSTRIDE];

    int tid = threadIdx.x;
    int lane = tid & 31;
    int wid  = tid >> 5;
    int gid  = lane >> 2;   // 0..7
    int tig  = lane & 3;    // 0..3
    int wm = (wid & 1) * 64;
    int wn = (wid >> 1) * 32;
    int m0 = blockIdx.x * BM;
    int n0 = blockIdx.y * BN;

    // staging mapping
    int arow0 = tid >> 2;   // 0..63 (+64)
    int ac4   = tid & 3;    // k quad
    int brow0 = tid >> 5;   // 0..7 (+8)
    int bc4   = tid & 31;   // n quad

    float acc[4][4][4];
#pragma unroll
    for (int i = 0; i < 4; i++)
#pragma unroll
        for (int j = 0; j < 4; j++)
#pragma unroll
            for (int r = 0; r < 4; r++) acc[i][j][r] = 0.f;

    float4 pa0, pa1, pb0, pb1;
    {
        int m = m0 + arow0;
        pa0 = (m < M) ? *(const float4*)&A[(size_t)m * 256 + ac4 * 4]
                      : make_float4(0.f, 0.f, 0.f, 0.f);
        m = m0 + arow0 + 64;
        pa1 = (m < M) ? *(const float4*)&A[(size_t)m * 256 + ac4 * 4]
                      : make_float4(0.f, 0.f, 0.f, 0.f);
        pb0 = *(const float4*)&W[(size_t)brow0 * 256 + n0 + bc4 * 4];
        pb1 = *(const float4*)&W[(size_t)(brow0 + 8) * 256 + n0 + bc4 * 4];
    }
    // store stage 0 (tf32-rounded)
    {
        As[0][ac4 * 4 + 0][arow0] = __uint_as_float(to_tf32(pa0.x));
        As[0][ac4 * 4 + 1][arow0] = __uint_as_float(to_tf32(pa0.y));
        As[0][ac4 * 4 + 2][arow0] = __uint_as_float(to_tf32(pa0.z));
        As[0][ac4 * 4 + 3][arow0] = __uint_as_float(to_tf32(pa0.w));
        As[0][ac4 * 4 + 0][arow0 + 64] = __uint_as_float(to_tf32(pa1.x));
        As[0][ac4 * 4 + 1][arow0 + 64] = __uint_as_float(to_tf32(pa1.y));
        As[0][ac4 * 4 + 2][arow0 + 64] = __uint_as_float(to_tf32(pa1.z));
        As[0][ac4 * 4 + 3][arow0 + 64] = __uint_as_float(to_tf32(pa1.w));
        float4 q0 = make_float4(__uint_as_float(to_tf32(pb0.x)), __uint_as_float(to_tf32(pb0.y)),
                                __uint_as_float(to_tf32(pb0.z)), __uint_as_float(to_tf32(pb0.w)));
        float4 q1 = make_float4(__uint_as_float(to_tf32(pb1.x)), __uint_as_float(to_tf32(pb1.y)),
                                __uint_as_float(to_tf32(pb1.z)), __uint_as_float(to_tf32(pb1.w)));
        *(float4*)&Bs[0][brow0][bc4 * 4]     = q0;
        *(float4*)&Bs[0][brow0 + 8][bc4 * 4] = q1;
    }
    __syncthreads();

    int buf = 0;
    for (int k0 = 0; k0 < 256; k0 += BK) {
        bool has_next = (k0 + BK) < 256;
        if (has_next) {
            int kb = k0 + BK;
            int m = m0 + arow0;
            pa0 = (m < M) ? *(const float4*)&A[(size_t)m * 256 + kb + ac4 * 4]
                          : make_float4(0.f, 0.f, 0.f, 0.f);
            m = m0 + arow0 + 64;
            pa1 = (m < M) ? *(const float4*)&A[(size_t)m * 256 + kb + ac4 * 4]
                          : make_float4(0.f, 0.f, 0.f, 0.f);
            pb0 = *(const float4*)&W[(size_t)(kb + brow0) * 256 + n0 + bc4 * 4];
            pb1 = *(const float4*)&W[(size_t)(kb + brow0 + 8) * 256 + n0 + bc4 * 4];
        }

        // compute on current buffer: 2 k-steps of 8
#pragma unroll
        for (int ks = 0; ks < 2; ks++) {
            int kb = ks * 8;
            uint32_t af[4][4];
            uint32_t bf[4][2];
#pragma unroll
            for (int mt = 0; mt < 4; mt++) {
                int m = wm + mt * 16 + gid;
                af[mt][0] = __float_as_uint(As[buf][kb + tig][m]);
                af[mt][1] = __float_as_uint(As[buf][kb + tig][m + 8]);
                af[mt][2] = __float_as_uint(As[buf][kb + tig + 4][m]);
                af[mt][3] = __float_as_uint(As[buf][kb + tig + 4][m + 8]);
            }
#pragma unroll
            for (int nt = 0; nt < 4; nt++) {
                int nn = wn + nt * 8 + gid;
                bf[nt][0] = __float_as_uint(Bs[buf][kb + tig][nn]);
                bf[nt][1] = __float_as_uint(Bs[buf][kb + tig + 4][nn]);
            }
#pragma unroll
            for (int mt = 0; mt < 4; mt++)
#pragma unroll
                for (int nt = 0; nt < 4; nt++)
                    mma_tf32(acc[mt][nt], af[mt], bf[nt]);
        }

        if (has_next) {
            int nb = buf ^ 1;
            As[nb][ac4 * 4 + 0][arow0] = __uint_as_float(to_tf32(pa0.x));
            As[nb][ac4 * 4 + 1][arow0] = __uint_as_float(to_tf32(pa0.y));
            As[nb][ac4 * 4 + 2][arow0] = __uint_as_float(to_tf32(pa0.z));
            As[nb][ac4 * 4 + 3][arow0] = __uint_as_float(to_tf32(pa0.w));
            As[nb][ac4 * 4 + 0][arow0 + 64] = __uint_as_float(to_tf32(pa1.x));
            As[nb][ac4 * 4 + 1][arow0 + 64] = __uint_as_float(to_tf32(pa1.y));
            As[nb][ac4 * 4 + 2][arow0 + 64] = __uint_as_float(to_tf32(pa1.z));
            As[nb][ac4 * 4 + 3][arow0 + 64] = __uint_as_float(to_tf32(pa1.w));
            float4 q0 = make_float4(__uint_as_float(to_tf32(pb0.x)), __uint_as_float(to_tf32(pb0.y)),
                                    __uint_as_float(to_tf32(pb0.z)), __uint_as_float(to_tf32(pb0.w)));
            float4 q1 = make_float4(__uint_as_float(to_tf32(pb1.x)), __uint_as_float(to_tf32(pb1.y)),
                                    __uint_as_float(to_tf32(pb1.z)), __uint_as_float(to_tf32(pb1.w)));
            *(float4*)&Bs[nb][brow0][bc4 * 4]     = q0;
            *(float4*)&Bs[nb][brow0 + 8][bc4 * 4] = q1;
            __syncthreads();
            buf = nb;
        }
    }

    // epilogue
#pragma unroll
    for (int mt = 0; mt < 4; mt++) {
#pragma unroll
        for (int nt = 0; nt < 4; nt++) {
            int r0 = m0 + wm + mt * 16 + gid;
            int col = n0 + wn + nt * 8 + tig * 2;
            if (r0 < M)
                *(float2*)&C[(size_t)r0 * 256 + col] =
                    make_float2(acc[mt][nt][0], acc[mt][nt][1]);
            if (r0 + 8 < M)
                *(float2*)&C[(size_t)(r0 + 8) * 256 + col] =
                    make_float2(acc[mt][nt][2], acc[mt][nt][3]);
        }
    }
}

// ---------------- fused aggregate + bias + LayerNorm + LeakyReLU ----------
__global__ void k_agg_ln(const float* __restrict__ h, float* __restrict__ out,
                         const float* __restrict__ bias,
                         const float* __restrict__ lnw,
                         const float* __restrict__ lnb) {
    int warp = (blockIdx.x * blockDim.x + threadIdx.x) >> 5;
    int lane = threadIdx.x & 31;
    if (warp >= N_NODES) return;
    int node = warp;
    int c0 = lane * 2;

    float di = g_dinv[node];
    const float4* selfrow = (const float4*)(h + (size_t)node * HID);
    float4 a0 = selfrow[c0];
    float4 a1 = selfrow[c0 + 1];
    float ws = di * di;
    a0.x *= ws; a0.y *= ws; a0.z *= ws; a0.w *= ws;
    a1.x *= ws; a1.y *= ws; a1.z *= ws; a1.w *= ws;

    float4 c0v = make_float4(0.f, 0.f, 0.f, 0.f);
    float4 c1v = make_float4(0.f, 0.f, 0.f, 0.f);

    int beg = g_rowptr[node];
    int end = g_rowptr[node + 1];
    int e = beg;
    for (; e + 1 < end; e += 2) {
        int s1 = g_csr_src[e];
        int s2 = g_csr_src[e + 1];
        float w1 = g_dinv[s1] * di;
        float w2 = g_dinv[s2] * di;
        const float4* r1 = (const float4*)(h + (size_t)s1 * HID);
        const float4* r2 = (const float4*)(h + (size_t)s2 * HID);
        float4 x0 = r1[c0], x1 = r1[c0 + 1];
        float4 y0 = r2[c0], y1 = r2[c0 + 1];
        a0.x += x0.x * w1; a0.y += x0.y * w1; a0.z += x0.z * w1; a0.w += x0.w * w1;
        a1.x += x1.x * w1; a1.y += x1.y * w1; a1.z += x1.z * w1; a1.w += x1.w * w1;
        c0v.x += y0.x * w2; c0v.y += y0.y * w2; c0v.z += y0.z * w2; c0v.w += y0.w * w2;
        c1v.x += y1.x * w2; c1v.y += y1.y * w2; c1v.z += y1.z * w2; c1v.w += y1.w * w2;
    }
    if (e < end) {
        int s = g_csr_src[e];
        float wv = g_dinv[s] * di;
        const float4* r = (const float4*)(h + (size_t)s * HID);
        float4 x0 = r[c0], x1 = r[c0 + 1];
        a0.x += x0.x * wv; a0.y += x0.y * wv; a0.z += x0.z * wv; a0.w += x0.w * wv;
        a1.x += x1.x * wv; a1.y += x1.y * wv; a1.z += x1.z * wv; a1.w += x1.w * wv;
    }
    a0.x += c0v.x; a0.y += c0v.y; a0.z += c0v.z; a0.w += c0v.w;
    a1.x += c1v.x; a1.y += c1v.y; a1.z += c1v.z; a1.w += c1v.w;

    float4 b0 = ((const float4*)bias)[c0];
    float4 b1 = ((const float4*)bias)[c0 + 1];
    a0.x += b0.x; a0.y += b0.y; a0.z += b0.z; a0.w += b0.w;
    a1.x += b1.x; a1.y += b1.y; a1.z += b1.z; a1.w += b1.w;

    float sum = a0.x + a0.y + a0.z + a0.w + a1.x + a1.y + a1.z + a1.w;
#pragma unroll
    for (int off = 16; off > 0; off >>= 1)
        sum += __shfl_xor_sync(0xffffffff, sum, off);
    float mu = sum * (1.0f / HID);

    float d0x = a0.x - mu, d0y = a0.y - mu, d0z = a0.z - mu, d0w = a0.w - mu;
    float d1x = a1.x - mu, d1y = a1.y - mu, d1z = a1.z - mu, d1w = a1.w - mu;
    float sq = d0x * d0x + d0y * d0y + d0z * d0z + d0w * d0w +
               d1x * d1x + d1y * d1y + d1z * d1z + d1w * d1w;
#pragma unroll
    for (int off = 16; off > 0; off >>= 1)
        sq += __shfl_xor_sync(0xffffffff, sq, off);
    float inv = rsqrtf(sq * (1.0f / HID) + LN_EPS);

    float4 w0 = ((const float4*)lnw)[c0];
    float4 w1 = ((const float4*)lnw)[c0 + 1];
    float4 lb0 = ((const float4*)lnb)[c0];
    float4 lb1 = ((const float4*)lnb)[c0 + 1];

    float v[8];
    v[0] = d0x * inv * w0.x + lb0.x;
    v[1] = d0y * inv * w0.y + lb0.y;
    v[2] = d0z * inv * w0.z + lb0.z;
    v[3] = d0w * inv * w0.w + lb0.w;
    v[4] = d1x * inv * w1.x + lb1.x;
    v[5] = d1y * inv * w1.y + lb1.y;
    v[6] = d1z * inv * w1.z + lb1.z;
    v[7] = d1w * inv * w1.w + lb1.w;
#pragma unroll
    for (int i = 0; i < 8; i++) v[i] = (v[i] >= 0.f) ? v[i] : LEAKY * v[i];

    float4* orow = (float4*)(out + (size_t)node * HID);
    orow[c0]     = make_float4(v[0], v[1], v[2], v[3]);
    orow[c0 + 1] = make_float4(v[4], v[5], v[6], v[7]);
}

// ---------------- per-graph mean pool ----------------
__global__ void k_pool(const float* __restrict__ h, const void* batch,
                       float* __restrict__ out) {
    int g = blockIdx.x;
    int is64 = g_is64;

    int lo = 0, hi = N_NODES;
    while (lo < hi) {
        int mid = (lo + hi) >> 1;
        if (load_idx(batch, mid, is64) < g) lo = mid + 1; else hi = mid;
    }
    int start = lo;
    hi = N_NODES;
    while (lo < hi) {
        int mid = (lo + hi) >> 1;
        if (load_idx(batch, mid, is64) < g + 1) lo = mid + 1; else hi = mid;
    }
    int end = lo;

    int t = threadIdx.x;
    float acc = 0.f;
    for (int i = start; i < end; i++)
        acc += h[(size_t)i * HID + t];
    float cnt = (float)(end - start);
    out[(size_t)g * HID + t] = acc / fmaxf(cnt, 1.f);
}

// ---------------- launch ----------------
extern "C" void kernel_launch(void* const* d_in, const int* in_sizes, int n_in,
                              void* d_out, int out_size) {
    const float* x    = (const float*)d_in[0];
    const void*  edge = d_in[1];
    const void*  batch= d_in[2];
    const float* W1   = (const float*)d_in[3];
    const float* b1   = (const float*)d_in[4];
    const float* ln1w = (const float*)d_in[5];
    const float* ln1b = (const float*)d_in[6];
    const float* W2   = (const float*)d_in[7];
    const float* b2   = (const float*)d_in[8];
    const float* ln2w = (const float*)d_in[9];
    const float* ln2b = (const float*)d_in[10];
    float* out = (float*)d_out;

    float *hA = nullptr, *hB = nullptr;
    cudaGetSymbolAddress((void**)&hA, g_hA);
    cudaGetSymbolAddress((void**)&hB, g_hB);

    const int TB = 256;
    int gN = (N_NODES + TB - 1) / TB;
    int gE = (N_EDGES + TB - 1) / TB;

    k_detect_init<<<gN + 1, TB>>>(edge, gN);
    k_count<<<gE, TB>>>(edge);
    k_scan<<<1, 1024>>>();
    k_scatter<<<gE, TB>>>(edge);

    dim3 gemmGrid((N_NODES + BM - 1) / BM, 256 / BN);
    int aggBlocks = (N_NODES * 32 + TB - 1) / TB;

    k_gemm<<<gemmGrid, TB>>>(x, W1, hA, N_NODES);
    k_agg_ln<<<aggBlocks, TB>>>(hA, hB, b1, ln1w, ln1b);

    k_gemm<<<gemmGrid, TB>>>(hB, W2, hA, N_NODES);
    k_agg_ln<<<aggBlocks, TB>>>(hA, hB, b2, ln2w, ln2b);

    k_pool<<<NUM_GRAPHS, HID>>>(hB, batch, out);
}

// round 5
// speedup vs baseline: 1.8266x; 1.0554x over previous
#include <cuda_runtime.h>
#include <math.h>
#include <stdint.h>

#define N_NODES   50000
#define N_EDGES   800000
#define HID       256
#define NUM_GRAPHS 512
#define LEAKY     0.01f
#define LN_EPS    1e-5f

// ---------------- device scratch ----------------
__device__ int   g_is64;
__device__ int   g_deg[N_NODES];
__device__ float g_dinv[N_NODES];
__device__ int   g_rowptr[N_NODES + 1];
__device__ int   g_cursor[N_NODES];
__device__ int   g_csr_src[N_EDGES];
__device__ float g_hA[(size_t)N_NODES * HID];
__device__ float g_hB[(size_t)N_NODES * HID];

__device__ __forceinline__ int load_idx(const void* p, long long i, int is64) {
    return is64 ? (int)((const long long*)p)[i] : ((const int*)p)[i];
}

__device__ __forceinline__ uint32_t to_tf32(float x) {
    uint32_t r;
    asm("cvt.rna.tf32.f32 %0, %1;" : "=r"(r) : "f"(x));
    return r;
}

// ---------------- fused: init deg + dtype detect ----------------
__global__ void k_detect_init(const void* edge, int gN) {
    if (blockIdx.x < gN) {
        int i = blockIdx.x * blockDim.x + threadIdx.x;
        if (i < N_NODES) g_deg[i] = 1;
        return;
    }
    __shared__ int any;
    if (threadIdx.x == 0) any = 0;
    __syncthreads();
    const int* w = (const int*)edge;
    int local = 0;
    for (int i = threadIdx.x; i < 1024; i += blockDim.x)
        if (w[2 * i + 1] != 0) local = 1;
    if (local) atomicOr(&any, 1);
    __syncthreads();
    if (threadIdx.x == 0) g_is64 = (any == 0) ? 1 : 0;
}

__global__ void k_count(const void* edge) {
    int e = blockIdx.x * blockDim.x + threadIdx.x;
    if (e >= N_EDGES) return;
    int is64 = g_is64;
    int d = load_idx(edge, (long long)N_EDGES + e, is64);
    atomicAdd(&g_deg[d], 1);
}

// ---------------- single-block scan, 2 elems/thread (+ fused dinv) -------
__global__ void k_scan() {
    __shared__ int wsum[32];
    __shared__ int carry_s;
    if (threadIdx.x == 0) carry_s = 0;
    __syncthreads();

    const int n = N_NODES;
    int tid  = threadIdx.x;
    int lane = tid & 31;
    int wid  = tid >> 5;
    const int CH = 2048;
    int nchunks = (n + CH - 1) / CH;

    for (int c = 0; c < nchunks; c++) {
        int i0 = c * CH + tid * 2;
        int d0 = (i0     < n) ? g_deg[i0]     : 1;
        int d1 = (i0 + 1 < n) ? g_deg[i0 + 1] : 1;
        int v0 = (i0     < n) ? (d0 - 1) : 0;
        int v1 = (i0 + 1 < n) ? (d1 - 1) : 0;
        int v = v0 + v1;

        int x = v;
#pragma unroll
        for (int off = 1; off < 32; off <<= 1) {
            int t = __shfl_up_sync(0xffffffff, x, off);
            if (lane >= off) x += t;
        }
        if (lane == 31) wsum[wid] = x;
        __syncthreads();
        if (wid == 0) {
            int y = wsum[lane];
#pragma unroll
            for (int off = 1; off < 32; off <<= 1) {
                int t = __shfl_up_sync(0xffffffff, y, off);
                if (lane >= off) y += t;
            }
            wsum[lane] = y;
        }
        __syncthreads();

        int carry = carry_s;
        int base = carry + (wid ? wsum[wid - 1] : 0) + x - v;  // exclusive for elem 0
        if (i0 < n) {
            g_rowptr[i0] = base;
            g_cursor[i0] = base;
            g_dinv[i0]   = rsqrtf((float)d0);
        }
        if (i0 + 1 < n) {
            g_rowptr[i0 + 1] = base + v0;
            g_cursor[i0 + 1] = base + v0;
            g_dinv[i0 + 1]   = rsqrtf((float)d1);
        }
        __syncthreads();
        if (tid == 0) carry_s = carry + wsum[31];
        __syncthreads();
    }
    if (tid == 0) g_rowptr[n] = carry_s;
}

__global__ void k_scatter(const void* edge) {
    int e = blockIdx.x * blockDim.x + threadIdx.x;
    if (e >= N_EDGES) return;
    int is64 = g_is64;
    int srce = load_idx(edge, e, is64);
    int dste = load_idx(edge, (long long)N_EDGES + e, is64);
    int pos = atomicAdd(&g_cursor[dste], 1);
    g_csr_src[pos] = srce;
}

// ---------------- tf32 tensor-core GEMM: C[M,256] = A @ W ----------------
#define BM 128
#define BN 128
#define BK 16
#define ASTRIDE (BM + 8)
#define BSTRIDE (BN + 8)

__device__ __forceinline__ void mma_tf32(float* c, const uint32_t* a, const uint32_t* b) {
    asm volatile(
        "mma.sync.aligned.m16n8k8.row.col.f32.tf32.tf32.f32 "
        "{%0,%1,%2,%3}, {%4,%5,%6,%7}, {%8,%9}, {%0,%1,%2,%3};"
        : "+f"(c[0]), "+f"(c[1]), "+f"(c[2]), "+f"(c[3])
        : "r"(a[0]), "r"(a[1]), "r"(a[2]), "r"(a[3]), "r"(b[0]), "r"(b[1]));
}

__global__ void __launch_bounds__(256)
k_gemm(const float* __restrict__ A, const float* __restrict__ W,
       float* __restrict__ C, int M) {
    __shared__ float As[2][BK][ASTRIDE];
    __shared__ float Bs[2][BK][BSTRIDE];

    int tid = threadIdx.x;
    int lane = tid & 31;
    int wid  = tid >> 5;
    int gid  = lane >> 2;
    int tig  = lane & 3;
    int wm = (wid & 1) * 64;
    int wn = (wid >> 1) * 32;
    int m0 = blockIdx.x * BM;
    int n0 = blockIdx.y * BN;

    int arow0 = tid >> 2;
    int ac4   = tid & 3;
    int brow0 = tid >> 5;
    int bc4   = tid & 31;

    float acc[4][4][4];
#pragma unroll
    for (int i = 0; i < 4; i++)
#pragma unroll
        for (int j = 0; j < 4; j++)
#pragma unroll
            for (int r = 0; r < 4; r++) acc[i][j][r] = 0.f;

    float4 pa0, pa1, pb0, pb1;
    {
        int m = m0 + arow0;
        pa0 = (m < M) ? *(const float4*)&A[(size_t)m * 256 + ac4 * 4]
                      : make_float4(0.f, 0.f, 0.f, 0.f);
        m = m0 + arow0 + 64;
        pa1 = (m < M) ? *(const float4*)&A[(size_t)m * 256 + ac4 * 4]
                      : make_float4(0.f, 0.f, 0.f, 0.f);
        pb0 = *(const float4*)&W[(size_t)brow0 * 256 + n0 + bc4 * 4];
        pb1 = *(const float4*)&W[(size_t)(brow0 + 8) * 256 + n0 + bc4 * 4];
    }
    {
        As[0][ac4 * 4 + 0][arow0] = __uint_as_float(to_tf32(pa0.x));
        As[0][ac4 * 4 + 1][arow0] = __uint_as_float(to_tf32(pa0.y));
        As[0][ac4 * 4 + 2][arow0] = __uint_as_float(to_tf32(pa0.z));
        As[0][ac4 * 4 + 3][arow0] = __uint_as_float(to_tf32(pa0.w));
        As[0][ac4 * 4 + 0][arow0 + 64] = __uint_as_float(to_tf32(pa1.x));
        As[0][ac4 * 4 + 1][arow0 + 64] = __uint_as_float(to_tf32(pa1.y));
        As[0][ac4 * 4 + 2][arow0 + 64] = __uint_as_float(to_tf32(pa1.z));
        As[0][ac4 * 4 + 3][arow0 + 64] = __uint_as_float(to_tf32(pa1.w));
        float4 q0 = make_float4(__uint_as_float(to_tf32(pb0.x)), __uint_as_float(to_tf32(pb0.y)),
                                __uint_as_float(to_tf32(pb0.z)), __uint_as_float(to_tf32(pb0.w)));
        float4 q1 = make_float4(__uint_as_float(to_tf32(pb1.x)), __uint_as_float(to_tf32(pb1.y)),
                                __uint_as_float(to_tf32(pb1.z)), __uint_as_float(to_tf32(pb1.w)));
        *(float4*)&Bs[0][brow0][bc4 * 4]     = q0;
        *(float4*)&Bs[0][brow0 + 8][bc4 * 4] = q1;
    }
    __syncthreads();

    int buf = 0;
    for (int k0 = 0; k0 < 256; k0 += BK) {
        bool has_next = (k0 + BK) < 256;
        if (has_next) {
            int kb = k0 + BK;
            int m = m0 + arow0;
            pa0 = (m < M) ? *(const float4*)&A[(size_t)m * 256 + kb + ac4 * 4]
                          : make_float4(0.f, 0.f, 0.f, 0.f);
            m = m0 + arow0 + 64;
            pa1 = (m < M) ? *(const float4*)&A[(size_t)m * 256 + kb + ac4 * 4]
                          : make_float4(0.f, 0.f, 0.f, 0.f);
            pb0 = *(const float4*)&W[(size_t)(kb + brow0) * 256 + n0 + bc4 * 4];
            pb1 = *(const float4*)&W[(size_t)(kb + brow0 + 8) * 256 + n0 + bc4 * 4];
        }

#pragma unroll
        for (int ks = 0; ks < 2; ks++) {
            int kb = ks * 8;
            uint32_t af[4][4];
            uint32_t bf[4][2];
#pragma unroll
            for (int mt = 0; mt < 4; mt++) {
                int m = wm + mt * 16 + gid;
                af[mt][0] = __float_as_uint(As[buf][kb + tig][m]);
                af[mt][1] = __float_as_uint(As[buf][kb + tig][m + 8]);
                af[mt][2] = __float_as_uint(As[buf][kb + tig + 4][m]);
                af[mt][3] = __float_as_uint(As[buf][kb + tig + 4][m + 8]);
            }
#pragma unroll
            for (int nt = 0; nt < 4; nt++) {
                int nn = wn + nt * 8 + gid;
                bf[nt][0] = __float_as_uint(Bs[buf][kb + tig][nn]);
                bf[nt][1] = __float_as_uint(Bs[buf][kb + tig + 4][nn]);
            }
#pragma unroll
            for (int mt = 0; mt < 4; mt++)
#pragma unroll
                for (int nt = 0; nt < 4; nt++)
                    mma_tf32(acc[mt][nt], af[mt], bf[nt]);
        }

        if (has_next) {
            int nb = buf ^ 1;
            As[nb][ac4 * 4 + 0][arow0] = __uint_as_float(to_tf32(pa0.x));
            As[nb][ac4 * 4 + 1][arow0] = __uint_as_float(to_tf32(pa0.y));
            As[nb][ac4 * 4 + 2][arow0] = __uint_as_float(to_tf32(pa0.z));
            As[nb][ac4 * 4 + 3][arow0] = __uint_as_float(to_tf32(pa0.w));
            As[nb][ac4 * 4 + 0][arow0 + 64] = __uint_as_float(to_tf32(pa1.x));
            As[nb][ac4 * 4 + 1][arow0 + 64] = __uint_as_float(to_tf32(pa1.y));
            As[nb][ac4 * 4 + 2][arow0 + 64] = __uint_as_float(to_tf32(pa1.z));
            As[nb][ac4 * 4 + 3][arow0 + 64] = __uint_as_float(to_tf32(pa1.w));
            float4 q0 = make_float4(__uint_as_float(to_tf32(pb0.x)), __uint_as_float(to_tf32(pb0.y)),
                                    __uint_as_float(to_tf32(pb0.z)), __uint_as_float(to_tf32(pb0.w)));
            float4 q1 = make_float4(__uint_as_float(to_tf32(pb1.x)), __uint_as_float(to_tf32(pb1.y)),
                                    __uint_as_float(to_tf32(pb1.z)), __uint_as_float(to_tf32(pb1.w)));
            *(float4*)&Bs[nb][brow0][bc4 * 4]     = q0;
            *(float4*)&Bs[nb][brow0 + 8][bc4 * 4] = q1;
            __syncthreads();
            buf = nb;
        }
    }

#pragma unroll
    for (int mt = 0; mt < 4; mt++) {
#pragma unroll
        for (int nt = 0; nt < 4; nt++) {
            int r0 = m0 + wm + mt * 16 + gid;
            int col = n0 + wn + nt * 8 + tig * 2;
            if (r0 < M)
                *(float2*)&C[(size_t)r0 * 256 + col] =
                    make_float2(acc[mt][nt][0], acc[mt][nt][1]);
            if (r0 + 8 < M)
                *(float2*)&C[(size_t)(r0 + 8) * 256 + col] =
                    make_float2(acc[mt][nt][2], acc[mt][nt][3]);
        }
    }
}

// ---------------- fused aggregate + bias + LayerNorm + LeakyReLU ----------
__global__ void k_agg_ln(const float* __restrict__ h, float* __restrict__ out,
                         const float* __restrict__ bias,
                         const float* __restrict__ lnw,
                         const float* __restrict__ lnb) {
    int warp = (blockIdx.x * blockDim.x + threadIdx.x) >> 5;
    int lane = threadIdx.x & 31;
    if (warp >= N_NODES) return;
    int node = warp;
    int c0 = lane * 2;

    float di = g_dinv[node];
    const float4* selfrow = (const float4*)(h + (size_t)node * HID);
    float4 a0 = selfrow[c0];
    float4 a1 = selfrow[c0 + 1];
    float ws = di * di;
    a0.x *= ws; a0.y *= ws; a0.z *= ws; a0.w *= ws;
    a1.x *= ws; a1.y *= ws; a1.z *= ws; a1.w *= ws;

    float4 c0v = make_float4(0.f, 0.f, 0.f, 0.f);
    float4 c1v = make_float4(0.f, 0.f, 0.f, 0.f);

    int beg = g_rowptr[node];
    int end = g_rowptr[node + 1];
    int e = beg;
    for (; e + 1 < end; e += 2) {
        int s1 = g_csr_src[e];
        int s2 = g_csr_src[e + 1];
        float w1 = g_dinv[s1] * di;
        float w2 = g_dinv[s2] * di;
        const float4* r1 = (const float4*)(h + (size_t)s1 * HID);
        const float4* r2 = (const float4*)(h + (size_t)s2 * HID);
        float4 x0 = r1[c0], x1 = r1[c0 + 1];
        float4 y0 = r2[c0], y1 = r2[c0 + 1];
        a0.x += x0.x * w1; a0.y += x0.y * w1; a0.z += x0.z * w1; a0.w += x0.w * w1;
        a1.x += x1.x * w1; a1.y += x1.y * w1; a1.z += x1.z * w1; a1.w += x1.w * w1;
        c0v.x += y0.x * w2; c0v.y += y0.y * w2; c0v.z += y0.z * w2; c0v.w += y0.w * w2;
        c1v.x += y1.x * w2; c1v.y += y1.y * w2; c1v.z += y1.z * w2; c1v.w += y1.w * w2;
    }
    if (e < end) {
        int s = g_csr_src[e];
        float wv = g_dinv[s] * di;
        const float4* r = (const float4*)(h + (size_t)s * HID);
        float4 x0 = r[c0], x1 = r[c0 + 1];
        a0.x += x0.x * wv; a0.y += x0.y * wv; a0.z += x0.z * wv; a0.w += x0.w * wv;
        a1.x += x1.x * wv; a1.y += x1.y * wv; a1.z += x1.z * wv; a1.w += x1.w * wv;
    }
    a0.x += c0v.x; a0.y += c0v.y; a0.z += c0v.z; a0.w += c0v.w;
    a1.x += c1v.x; a1.y += c1v.y; a1.z += c1v.z; a1.w += c1v.w;

    float4 b0 = ((const float4*)bias)[c0];
    float4 b1 = ((const float4*)bias)[c0 + 1];
    a0.x += b0.x; a0.y += b0.y; a0.z += b0.z; a0.w += b0.w;
    a1.x += b1.x; a1.y += b1.y; a1.z += b1.z; a1.w += b1.w;

    float sum = a0.x + a0.y + a0.z + a0.w + a1.x + a1.y + a1.z + a1.w;
#pragma unroll
    for (int off = 16; off > 0; off >>= 1)
        sum += __shfl_xor_sync(0xffffffff, sum, off);
    float mu = sum * (1.0f / HID);

    float d0x = a0.x - mu, d0y = a0.y - mu, d0z = a0.z - mu, d0w = a0.w - mu;
    float d1x = a1.x - mu, d1y = a1.y - mu, d1z = a1.z - mu, d1w = a1.w - mu;
    float sq = d0x * d0x + d0y * d0y + d0z * d0z + d0w * d0w +
               d1x * d1x + d1y * d1y + d1z * d1z + d1w * d1w;
#pragma unroll
    for (int off = 16; off > 0; off >>= 1)
        sq += __shfl_xor_sync(0xffffffff, sq, off);
    float inv = rsqrtf(sq * (1.0f / HID) + LN_EPS);

    float4 w0 = ((const float4*)lnw)[c0];
    float4 w1 = ((const float4*)lnw)[c0 + 1];
    float4 lb0 = ((const float4*)lnb)[c0];
    float4 lb1 = ((const float4*)lnb)[c0 + 1];

    float v[8];
    v[0] = d0x * inv * w0.x + lb0.x;
    v[1] = d0y * inv * w0.y + lb0.y;
    v[2] = d0z * inv * w0.z + lb0.z;
    v[3] = d0w * inv * w0.w + lb0.w;
    v[4] = d1x * inv * w1.x + lb1.x;
    v[5] = d1y * inv * w1.y + lb1.y;
    v[6] = d1z * inv * w1.z + lb1.z;
    v[7] = d1w * inv * w1.w + lb1.w;
#pragma unroll
    for (int i = 0; i < 8; i++) v[i] = (v[i] >= 0.f) ? v[i] : LEAKY * v[i];

    float4* orow = (float4*)(out + (size_t)node * HID);
    orow[c0]     = make_float4(v[0], v[1], v[2], v[3]);
    orow[c0 + 1] = make_float4(v[4], v[5], v[6], v[7]);
}

// ---------------- per-graph mean pool ----------------
__global__ void k_pool(const float* __restrict__ h, const void* batch,
                       float* __restrict__ out) {
    int g = blockIdx.x;
    int is64 = g_is64;

    int lo = 0, hi = N_NODES;
    while (lo < hi) {
        int mid = (lo + hi) >> 1;
        if (load_idx(batch, mid, is64) < g) lo = mid + 1; else hi = mid;
    }
    int start = lo;
    hi = N_NODES;
    while (lo < hi) {
        int mid = (lo + hi) >> 1;
        if (load_idx(batch, mid, is64) < g + 1) lo = mid + 1; else hi = mid;
    }
    int end = lo;

    int t = threadIdx.x;
    float acc = 0.f;
    for (int i = start; i < end; i++)
        acc += h[(size_t)i * HID + t];
    float cnt = (float)(end - start);
    out[(size_t)g * HID + t] = acc / fmaxf(cnt, 1.f);
}

// ---------------- launch ----------------
extern "C" void kernel_launch(void* const* d_in, const int* in_sizes, int n_in,
                              void* d_out, int out_size) {
    const float* x    = (const float*)d_in[0];
    const void*  edge = d_in[1];
    const void*  batch= d_in[2];
    const float* W1   = (const float*)d_in[3];
    const float* b1   = (const float*)d_in[4];
    const float* ln1w = (const float*)d_in[5];
    const float* ln1b = (const float*)d_in[6];
    const float* W2   = (const float*)d_in[7];
    const float* b2   = (const float*)d_in[8];
    const float* ln2w = (const float*)d_in[9];
    const float* ln2b = (const float*)d_in[10];
    float* out = (float*)d_out;

    float *hA = nullptr, *hB = nullptr;
    cudaGetSymbolAddress((void**)&hA, g_hA);
    cudaGetSymbolAddress((void**)&hB, g_hB);

    // side stream + fork/join events, created once on the (uncaptured)
    // correctness call; replayed identically inside the graph thereafter.
    static cudaStream_t s_side = nullptr;
    static cudaEvent_t  s_fork = nullptr, s_join = nullptr;
    static int s_ok = -1;
    if (s_ok < 0) {
        s_ok = 1;
        if (cudaStreamCreateWithFlags(&s_side, cudaStreamNonBlocking) != cudaSuccess) s_ok = 0;
        if (s_ok && cudaEventCreateWithFlags(&s_fork, cudaEventDisableTiming) != cudaSuccess) s_ok = 0;
        if (s_ok && cudaEventCreateWithFlags(&s_join, cudaEventDisableTiming) != cudaSuccess) s_ok = 0;
    }
    cudaStream_t side = s_ok ? s_side : (cudaStream_t)0;

    const int TB = 256;
    int gN = (N_NODES + TB - 1) / TB;
    int gE = (N_EDGES + TB - 1) / TB;

    dim3 gemmGrid((N_NODES + BM - 1) / BM, 256 / BN);
    int aggBlocks = (N_NODES * 32 + TB - 1) / TB;

    // fork: CSR build on side stream, GEMM1 on main stream (independent)
    if (s_ok) {
        cudaEventRecord(s_fork, 0);
        cudaStreamWaitEvent(side, s_fork, 0);
    }

    k_gemm<<<gemmGrid, TB>>>(x, W1, hA, N_NODES);            // main stream

    k_detect_init<<<gN + 1, TB, 0, side>>>(edge, gN);        // side stream
    k_count<<<gE, TB, 0, side>>>(edge);
    k_scan<<<1, 1024, 0, side>>>();
    k_scatter<<<gE, TB, 0, side>>>(edge);

    if (s_ok) {
        cudaEventRecord(s_join, side);
        cudaStreamWaitEvent(0, s_join, 0);
    }

    // join: agg1 needs both GEMM1 output and the CSR
    k_agg_ln<<<aggBlocks, TB>>>(hA, hB, b1, ln1w, ln1b);

    k_gemm<<<gemmGrid, TB>>>(hB, W2, hA, N_NODES);
    k_agg_ln<<<aggBlocks, TB>>>(hA, hB, b2, ln2w, ln2b);

    k_pool<<<NUM_GRAPHS, HID>>>(hB, batch, out);
}

// round 6
// speedup vs baseline: 1.9912x; 1.0902x over previous
#include <cuda_runtime.h>
#include <math.h>
#include <stdint.h>

#define N_NODES   50000
#define N_EDGES   800000
#define HID       256
#define NUM_GRAPHS 512
#define LEAKY     0.01f
#define LN_EPS    1e-5f

#define SCAN_CH   2048
#define SCAN_NBLK ((N_NODES + SCAN_CH - 1) / SCAN_CH)   // 25

// ---------------- device scratch ----------------
__device__ int   g_is64;
__device__ int   g_deg[N_NODES];
__device__ float g_dinv[N_NODES];
__device__ int   g_rowptr[N_NODES + 1];
__device__ int   g_cursor[N_NODES];
__device__ int   g_csr_src[N_EDGES];
__device__ int   g_bsum[SCAN_NBLK];
__device__ int   g_boff[SCAN_NBLK];
__device__ float g_hA[(size_t)N_NODES * HID];
__device__ float g_hB[(size_t)N_NODES * HID];

__device__ __forceinline__ int load_idx(const void* p, long long i, int is64) {
    return is64 ? (int)((const long long*)p)[i] : ((const int*)p)[i];
}

__device__ __forceinline__ uint32_t to_tf32(float x) {
    uint32_t r;
    asm("cvt.rna.tf32.f32 %0, %1;" : "=r"(r) : "f"(x));
    return r;
}

// ---------------- fused: init deg + dtype detect ----------------
__global__ void k_detect_init(const void* edge, int gN) {
    if (blockIdx.x < gN) {
        int i = blockIdx.x * blockDim.x + threadIdx.x;
        if (i < N_NODES) g_deg[i] = 1;
        return;
    }
    __shared__ int any;
    if (threadIdx.x == 0) any = 0;
    __syncthreads();
    const int* w = (const int*)edge;
    int local = 0;
    for (int i = threadIdx.x; i < 1024; i += blockDim.x)
        if (w[2 * i + 1] != 0) local = 1;
    if (local) atomicOr(&any, 1);
    __syncthreads();
    if (threadIdx.x == 0) g_is64 = (any == 0) ? 1 : 0;
}

__global__ void k_count(const void* edge) {
    int e = blockIdx.x * blockDim.x + threadIdx.x;
    if (e >= N_EDGES) return;
    int is64 = g_is64;
    int d = load_idx(edge, (long long)N_EDGES + e, is64);
    atomicAdd(&g_deg[d], 1);
}

// ---------------- parallel 3-pass scan ----------------
// pass 1: per-block local exclusive scan (2 elems/thread), dinv, block sums
__global__ void __launch_bounds__(1024) k_scan1() {
    __shared__ int wsum[32];
    int b    = blockIdx.x;
    int tid  = threadIdx.x;
    int lane = tid & 31;
    int wid  = tid >> 5;

    int i0 = b * SCAN_CH + tid * 2;
    int d0 = (i0     < N_NODES) ? g_deg[i0]     : 1;
    int d1 = (i0 + 1 < N_NODES) ? g_deg[i0 + 1] : 1;
    int v0 = (i0     < N_NODES) ? (d0 - 1) : 0;
    int v1 = (i0 + 1 < N_NODES) ? (d1 - 1) : 0;
    int v = v0 + v1;

    int x = v;
#pragma unroll
    for (int off = 1; off < 32; off <<= 1) {
        int t = __shfl_up_sync(0xffffffff, x, off);
        if (lane >= off) x += t;
    }
    if (lane == 31) wsum[wid] = x;
    __syncthreads();
    if (wid == 0) {
        int y = wsum[lane];
#pragma unroll
        for (int off = 1; off < 32; off <<= 1) {
            int t = __shfl_up_sync(0xffffffff, y, off);
            if (lane >= off) y += t;
        }
        wsum[lane] = y;
    }
    __syncthreads();

    int base = (wid ? wsum[wid - 1] : 0) + x - v;   // local exclusive
    if (i0 < N_NODES) {
        g_rowptr[i0] = base;                         // local, fixed in pass 3
        g_dinv[i0]   = rsqrtf((float)d0);
    }
    if (i0 + 1 < N_NODES) {
        g_rowptr[i0 + 1] = base + v0;
        g_dinv[i0 + 1]   = rsqrtf((float)d1);
    }
    if (tid == 0) g_bsum[b] = 0;                     // ensure defined
    __syncthreads();
    if (tid == 1023) g_bsum[b] = wsum[31];           // block total (inclusive of last)
}

// pass 2: one warp scans SCAN_NBLK block sums (SCAN_NBLK <= 32)
__global__ void k_scan2() {
    int lane = threadIdx.x;
    int v = (lane < SCAN_NBLK) ? g_bsum[lane] : 0;
    int x = v;
#pragma unroll
    for (int off = 1; off < 32; off <<= 1) {
        int t = __shfl_up_sync(0xffffffff, x, off);
        if (lane >= off) x += t;
    }
    if (lane < SCAN_NBLK) g_boff[lane] = x - v;      // exclusive offsets
    if (lane == 31) g_rowptr[N_NODES] = x;           // grand total
}

// pass 3: add block offsets, finalize rowptr + cursor
__global__ void k_scan3() {
    int i = blockIdx.x * blockDim.x + threadIdx.x;
    if (i >= N_NODES) return;
    int off = g_boff[i / SCAN_CH];
    int r = g_rowptr[i] + off;
    g_rowptr[i] = r;
    g_cursor[i] = r;
}

__global__ void k_scatter(const void* edge) {
    int e = blockIdx.x * blockDim.x + threadIdx.x;
    if (e >= N_EDGES) return;
    int is64 = g_is64;
    int srce = load_idx(edge, e, is64);
    int dste = load_idx(edge, (long long)N_EDGES + e, is64);
    int pos = atomicAdd(&g_cursor[dste], 1);
    g_csr_src[pos] = srce;
}

// ---------------- tf32 tensor-core GEMM: C[M,256] = A @ W ----------------
#define BM 128
#define BN 128
#define BK 16
#define ASTRIDE (BM + 8)
#define BSTRIDE (BN + 8)

__device__ __forceinline__ void mma_tf32(float* c, const uint32_t* a, const uint32_t* b) {
    asm volatile(
        "mma.sync.aligned.m16n8k8.row.col.f32.tf32.tf32.f32 "
        "{%0,%1,%2,%3}, {%4,%5,%6,%7}, {%8,%9}, {%0,%1,%2,%3};"
        : "+f"(c[0]), "+f"(c[1]), "+f"(c[2]), "+f"(c[3])
        : "r"(a[0]), "r"(a[1]), "r"(a[2]), "r"(a[3]), "r"(b[0]), "r"(b[1]));
}

__global__ void __launch_bounds__(256)
k_gemm(const float* __restrict__ A, const float* __restrict__ W,
       float* __restrict__ C, int M) {
    __shared__ float As[2][BK][ASTRIDE];
    __shared__ float Bs[2][BK][BSTRIDE];

    int tid = threadIdx.x;
    int lane = tid & 31;
    int wid  = tid >> 5;
    int gid  = lane >> 2;
    int tig  = lane & 3;
    int wm = (wid & 1) * 64;
    int wn = (wid >> 1) * 32;
    int m0 = blockIdx.x * BM;
    int n0 = blockIdx.y * BN;

    int arow0 = tid >> 2;
    int ac4   = tid & 3;
    int brow0 = tid >> 5;
    int bc4   = tid & 31;

    float acc[4][4][4];
#pragma unroll
    for (int i = 0; i < 4; i++)
#pragma unroll
        for (int j = 0; j < 4; j++)
#pragma unroll
            for (int r = 0; r < 4; r++) acc[i][j][r] = 0.f;

    float4 pa0, pa1, pb0, pb1;
    {
        int m = m0 + arow0;
        pa0 = (m < M) ? *(const float4*)&A[(size_t)m * 256 + ac4 * 4]
                      : make_float4(0.f, 0.f, 0.f, 0.f);
        m = m0 + arow0 + 64;
        pa1 = (m < M) ? *(const float4*)&A[(size_t)m * 256 + ac4 * 4]
                      : make_float4(0.f, 0.f, 0.f, 0.f);
        pb0 = *(const float4*)&W[(size_t)brow0 * 256 + n0 + bc4 * 4];
        pb1 = *(const float4*)&W[(size_t)(brow0 + 8) * 256 + n0 + bc4 * 4];
    }
    {
        As[0][ac4 * 4 + 0][arow0] = __uint_as_float(to_tf32(pa0.x));
        As[0][ac4 * 4 + 1][arow0] = __uint_as_float(to_tf32(pa0.y));
        As[0][ac4 * 4 + 2][arow0] = __uint_as_float(to_tf32(pa0.z));
        As[0][ac4 * 4 + 3][arow0] = __uint_as_float(to_tf32(pa0.w));
        As[0][ac4 * 4 + 0][arow0 + 64] = __uint_as_float(to_tf32(pa1.x));
        As[0][ac4 * 4 + 1][arow0 + 64] = __uint_as_float(to_tf32(pa1.y));
        As[0][ac4 * 4 + 2][arow0 + 64] = __uint_as_float(to_tf32(pa1.z));
        As[0][ac4 * 4 + 3][arow0 + 64] = __uint_as_float(to_tf32(pa1.w));
        float4 q0 = make_float4(__uint_as_float(to_tf32(pb0.x)), __uint_as_float(to_tf32(pb0.y)),
                                __uint_as_float(to_tf32(pb0.z)), __uint_as_float(to_tf32(pb0.w)));
        float4 q1 = make_float4(__uint_as_float(to_tf32(pb1.x)), __uint_as_float(to_tf32(pb1.y)),
                                __uint_as_float(to_tf32(pb1.z)), __uint_as_float(to_tf32(pb1.w)));
        *(float4*)&Bs[0][brow0][bc4 * 4]     = q0;
        *(float4*)&Bs[0][brow0 + 8][bc4 * 4] = q1;
    }
    __syncthreads();

    int buf = 0;
    for (int k0 = 0; k0 < 256; k0 += BK) {
        bool has_next = (k0 + BK) < 256;
        if (has_next) {
            int kb = k0 + BK;
            int m = m0 + arow0;
            pa0 = (m < M) ? *(const float4*)&A[(size_t)m * 256 + kb + ac4 * 4]
                          : make_float4(0.f, 0.f, 0.f, 0.f);
            m = m0 + arow0 + 64;
            pa1 = (m < M) ? *(const float4*)&A[(size_t)m * 256 + kb + ac4 * 4]
                          : make_float4(0.f, 0.f, 0.f, 0.f);
            pb0 = *(const float4*)&W[(size_t)(kb + brow0) * 256 + n0 + bc4 * 4];
            pb1 = *(const float4*)&W[(size_t)(kb + brow0 + 8) * 256 + n0 + bc4 * 4];
        }

#pragma unroll
        for (int ks = 0; ks < 2; ks++) {
            int kb = ks * 8;
            uint32_t af[4][4];
            uint32_t bf[4][2];
#pragma unroll
            for (int mt = 0; mt < 4; mt++) {
                int m = wm + mt * 16 + gid;
                af[mt][0] = __float_as_uint(As[buf][kb + tig][m]);
                af[mt][1] = __float_as_uint(As[buf][kb + tig][m + 8]);
                af[mt][2] = __float_as_uint(As[buf][kb + tig + 4][m]);
                af[mt][3] = __float_as_uint(As[buf][kb + tig + 4][m + 8]);
            }
#pragma unroll
            for (int nt = 0; nt < 4; nt++) {
                int nn = wn + nt * 8 + gid;
                bf[nt][0] = __float_as_uint(Bs[buf][kb + tig][nn]);
                bf[nt][1] = __float_as_uint(Bs[buf][kb + tig + 4][nn]);
            }
#pragma unroll
            for (int mt = 0; mt < 4; mt++)
#pragma unroll
                for (int nt = 0; nt < 4; nt++)
                    mma_tf32(acc[mt][nt], af[mt], bf[nt]);
        }

        if (has_next) {
            int nb = buf ^ 1;
            As[nb][ac4 * 4 + 0][arow0] = __uint_as_float(to_tf32(pa0.x));
            As[nb][ac4 * 4 + 1][arow0] = __uint_as_float(to_tf32(pa0.y));
            As[nb][ac4 * 4 + 2][arow0] = __uint_as_float(to_tf32(pa0.z));
            As[nb][ac4 * 4 + 3][arow0] = __uint_as_float(to_tf32(pa0.w));
            As[nb][ac4 * 4 + 0][arow0 + 64] = __uint_as_float(to_tf32(pa1.x));
            As[nb][ac4 * 4 + 1][arow0 + 64] = __uint_as_float(to_tf32(pa1.y));
            As[nb][ac4 * 4 + 2][arow0 + 64] = __uint_as_float(to_tf32(pa1.z));
            As[nb][ac4 * 4 + 3][arow0 + 64] = __uint_as_float(to_tf32(pa1.w));
            float4 q0 = make_float4(__uint_as_float(to_tf32(pb0.x)), __uint_as_float(to_tf32(pb0.y)),
                                    __uint_as_float(to_tf32(pb0.z)), __uint_as_float(to_tf32(pb0.w)));
            float4 q1 = make_float4(__uint_as_float(to_tf32(pb1.x)), __uint_as_float(to_tf32(pb1.y)),
                                    __uint_as_float(to_tf32(pb1.z)), __uint_as_float(to_tf32(pb1.w)));
            *(float4*)&Bs[nb][brow0][bc4 * 4]     = q0;
            *(float4*)&Bs[nb][brow0 + 8][bc4 * 4] = q1;
            __syncthreads();
            buf = nb;
        }
    }

#pragma unroll
    for (int mt = 0; mt < 4; mt++) {
#pragma unroll
        for (int nt = 0; nt < 4; nt++) {
            int r0 = m0 + wm + mt * 16 + gid;
            int col = n0 + wn + nt * 8 + tig * 2;
            if (r0 < M)
                *(float2*)&C[(size_t)r0 * 256 + col] =
                    make_float2(acc[mt][nt][0], acc[mt][nt][1]);
            if (r0 + 8 < M)
                *(float2*)&C[(size_t)(r0 + 8) * 256 + col] =
                    make_float2(acc[mt][nt][2], acc[mt][nt][3]);
        }
    }
}

// ---------------- fused aggregate + bias + LayerNorm + LeakyReLU ----------
__global__ void k_agg_ln(const float* __restrict__ h, float* __restrict__ out,
                         const float* __restrict__ bias,
                         const float* __restrict__ lnw,
                         const float* __restrict__ lnb) {
    int warp = (blockIdx.x * blockDim.x + threadIdx.x) >> 5;
    int lane = threadIdx.x & 31;
    if (warp >= N_NODES) return;
    int node = warp;
    int c0 = lane * 2;

    float di = g_dinv[node];
    const float4* selfrow = (const float4*)(h + (size_t)node * HID);
    float4 a0 = selfrow[c0];
    float4 a1 = selfrow[c0 + 1];
    float ws = di * di;
    a0.x *= ws; a0.y *= ws; a0.z *= ws; a0.w *= ws;
    a1.x *= ws; a1.y *= ws; a1.z *= ws; a1.w *= ws;

    float4 c0v = make_float4(0.f, 0.f, 0.f, 0.f);
    float4 c1v = make_float4(0.f, 0.f, 0.f, 0.f);

    int beg = g_rowptr[node];
    int end = g_rowptr[node + 1];
    int e = beg;
    for (; e + 1 < end; e += 2) {
        int s1 = g_csr_src[e];
        int s2 = g_csr_src[e + 1];
        float w1 = g_dinv[s1] * di;
        float w2 = g_dinv[s2] * di;
        const float4* r1 = (const float4*)(h + (size_t)s1 * HID);
        const float4* r2 = (const float4*)(h + (size_t)s2 * HID);
        float4 x0 = r1[c0], x1 = r1[c0 + 1];
        float4 y0 = r2[c0], y1 = r2[c0 + 1];
        a0.x += x0.x * w1; a0.y += x0.y * w1; a0.z += x0.z * w1; a0.w += x0.w * w1;
        a1.x += x1.x * w1; a1.y += x1.y * w1; a1.z += x1.z * w1; a1.w += x1.w * w1;
        c0v.x += y0.x * w2; c0v.y += y0.y * w2; c0v.z += y0.z * w2; c0v.w += y0.w * w2;
        c1v.x += y1.x * w2; c1v.y += y1.y * w2; c1v.z += y1.z * w2; c1v.w += y1.w * w2;
    }
    if (e < end) {
        int s = g_csr_src[e];
        float wv = g_dinv[s] * di;
        const float4* r = (const float4*)(h + (size_t)s * HID);
        float4 x0 = r[c0], x1 = r[c0 + 1];
        a0.x += x0.x * wv; a0.y += x0.y * wv; a0.z += x0.z * wv; a0.w += x0.w * wv;
        a1.x += x1.x * wv; a1.y += x1.y * wv; a1.z += x1.z * wv; a1.w += x1.w * wv;
    }
    a0.x += c0v.x; a0.y += c0v.y; a0.z += c0v.z; a0.w += c0v.w;
    a1.x += c1v.x; a1.y += c1v.y; a1.z += c1v.z; a1.w += c1v.w;

    float4 b0 = ((const float4*)bias)[c0];
    float4 b1 = ((const float4*)bias)[c0 + 1];
    a0.x += b0.x; a0.y += b0.y; a0.z += b0.z; a0.w += b0.w;
    a1.x += b1.x; a1.y += b1.y; a1.z += b1.z; a1.w += b1.w;

    float sum = a0.x + a0.y + a0.z + a0.w + a1.x + a1.y + a1.z + a1.w;
#pragma unroll
    for (int off = 16; off > 0; off >>= 1)
        sum += __shfl_xor_sync(0xffffffff, sum, off);
    float mu = sum * (1.0f / HID);

    float d0x = a0.x - mu, d0y = a0.y - mu, d0z = a0.z - mu, d0w = a0.w - mu;
    float d1x = a1.x - mu, d1y = a1.y - mu, d1z = a1.z - mu, d1w = a1.w - mu;
    float sq = d0x * d0x + d0y * d0y + d0z * d0z + d0w * d0w +
               d1x * d1x + d1y * d1y + d1z * d1z + d1w * d1w;
#pragma unroll
    for (int off = 16; off > 0; off >>= 1)
        sq += __shfl_xor_sync(0xffffffff, sq, off);
    float inv = rsqrtf(sq * (1.0f / HID) + LN_EPS);

    float4 w0 = ((const float4*)lnw)[c0];
    float4 w1 = ((const float4*)lnw)[c0 + 1];
    float4 lb0 = ((const float4*)lnb)[c0];
    float4 lb1 = ((const float4*)lnb)[c0 + 1];

    float v[8];
    v[0] = d0x * inv * w0.x + lb0.x;
    v[1] = d0y * inv * w0.y + lb0.y;
    v[2] = d0z * inv * w0.z + lb0.z;
    v[3] = d0w * inv * w0.w + lb0.w;
    v[4] = d1x * inv * w1.x + lb1.x;
    v[5] = d1y * inv * w1.y + lb1.y;
    v[6] = d1z * inv * w1.z + lb1.z;
    v[7] = d1w * inv * w1.w + lb1.w;
#pragma unroll
    for (int i = 0; i < 8; i++) v[i] = (v[i] >= 0.f) ? v[i] : LEAKY * v[i];

    float4* orow = (float4*)(out + (size_t)node * HID);
    orow[c0]     = make_float4(v[0], v[1], v[2], v[3]);
    orow[c0 + 1] = make_float4(v[4], v[5], v[6], v[7]);
}

// ---------------- per-graph mean pool ----------------
__global__ void k_pool(const float* __restrict__ h, const void* batch,
                       float* __restrict__ out) {
    int g = blockIdx.x;
    int is64 = g_is64;

    int lo = 0, hi = N_NODES;
    while (lo < hi) {
        int mid = (lo + hi) >> 1;
        if (load_idx(batch, mid, is64) < g) lo = mid + 1; else hi = mid;
    }
    int start = lo;
    hi = N_NODES;
    while (lo < hi) {
        int mid = (lo + hi) >> 1;
        if (load_idx(batch, mid, is64) < g + 1) lo = mid + 1; else hi = mid;
    }
    int end = lo;

    int t = threadIdx.x;
    float acc = 0.f;
    for (int i = start; i < end; i++)
        acc += h[(size_t)i * HID + t];
    float cnt = (float)(end - start);
    out[(size_t)g * HID + t] = acc / fmaxf(cnt, 1.f);
}

// ---------------- launch ----------------
extern "C" void kernel_launch(void* const* d_in, const int* in_sizes, int n_in,
                              void* d_out, int out_size) {
    const float* x    = (const float*)d_in[0];
    const void*  edge = d_in[1];
    const void*  batch= d_in[2];
    const float* W1   = (const float*)d_in[3];
    const float* b1   = (const float*)d_in[4];
    const float* ln1w = (const float*)d_in[5];
    const float* ln1b = (const float*)d_in[6];
    const float* W2   = (const float*)d_in[7];
    const float* b2   = (const float*)d_in[8];
    const float* ln2w = (const float*)d_in[9];
    const float* ln2b = (const float*)d_in[10];
    float* out = (float*)d_out;

    float *hA = nullptr, *hB = nullptr;
    cudaGetSymbolAddress((void**)&hA, g_hA);
    cudaGetSymbolAddress((void**)&hB, g_hB);

    static cudaStream_t s_side = nullptr;
    static cudaEvent_t  s_fork = nullptr, s_join = nullptr;
    static int s_ok = -1;
    if (s_ok < 0) {
        s_ok = 1;
        if (cudaStreamCreateWithFlags(&s_side, cudaStreamNonBlocking) != cudaSuccess) s_ok = 0;
        if (s_ok && cudaEventCreateWithFlags(&s_fork, cudaEventDisableTiming) != cudaSuccess) s_ok = 0;
        if (s_ok && cudaEventCreateWithFlags(&s_join, cudaEventDisableTiming) != cudaSuccess) s_ok = 0;
    }
    cudaStream_t side = s_ok ? s_side : (cudaStream_t)0;

    const int TB = 256;
    int gN = (N_NODES + TB - 1) / TB;
    int gE = (N_EDGES + TB - 1) / TB;

    dim3 gemmGrid((N_NODES + BM - 1) / BM, 256 / BN);
    int aggBlocks = (N_NODES * 32 + TB - 1) / TB;

    if (s_ok) {
        cudaEventRecord(s_fork, 0);
        cudaStreamWaitEvent(side, s_fork, 0);
    }

    k_gemm<<<gemmGrid, TB>>>(x, W1, hA, N_NODES);            // main stream

    k_detect_init<<<gN + 1, TB, 0, side>>>(edge, gN);        // side stream
    k_count<<<gE, TB, 0, side>>>(edge);
    k_scan1<<<SCAN_NBLK, 1024, 0, side>>>();
    k_scan2<<<1, 32, 0, side>>>();
    k_scan3<<<gN, TB, 0, side>>>();
    k_scatter<<<gE, TB, 0, side>>>(edge);

    if (s_ok) {
        cudaEventRecord(s_join, side);
        cudaStreamWaitEvent(0, s_join, 0);
    }

    k_agg_ln<<<aggBlocks, TB>>>(hA, hB, b1, ln1w, ln1b);

    k_gemm<<<gemmGrid, TB>>>(hB, W2, hA, N_NODES);
    k_agg_ln<<<aggBlocks, TB>>>(hA, hB, b2, ln2w, ln2b);

    k_pool<<<NUM_GRAPHS, HID>>>(hB, batch, out);
}

// round 7
// speedup vs baseline: 2.3374x; 1.1738x over previous
#include <cuda_runtime.h>
#include <cuda_fp16.h>
#include <math.h>
#include <stdint.h>

#define N_NODES   50000
#define N_EDGES   800000
#define HID       256
#define NUM_GRAPHS 512
#define LEAKY     0.01f
#define LN_EPS    1e-5f

#define SCAN_CH   2048
#define SCAN_NBLK ((N_NODES + SCAN_CH - 1) / SCAN_CH)   // 25

// ---------------- device scratch ----------------
__device__ int   g_is64;
__device__ int   g_deg[N_NODES];
__device__ float g_dinv[N_NODES];
__device__ int   g_rowptr[N_NODES + 1];
__device__ int   g_cursor[N_NODES];
__device__ int   g_csr_src[N_EDGES];
__device__ int   g_bsum[SCAN_NBLK];
__device__ int   g_boff[SCAN_NBLK];
__device__ __align__(16) __half g_h16A[(size_t)N_NODES * HID];  // GEMM out (both layers)
__device__ __align__(16) __half g_h16B[(size_t)N_NODES * HID];  // agg1 out
__device__ __align__(16) float  g_hC[(size_t)N_NODES * HID];    // agg2 out (fp32 for pool)

__device__ __forceinline__ int load_idx(const void* p, long long i, int is64) {
    return is64 ? (int)((const long long*)p)[i] : ((const int*)p)[i];
}

__device__ __forceinline__ uint32_t to_tf32(float x) {
    uint32_t r;
    asm("cvt.rna.tf32.f32 %0, %1;" : "=r"(r) : "f"(x));
    return r;
}

// load 8 halves (16B) -> 8 floats
__device__ __forceinline__ void load8h(const __half* p, float* f) {
    uint4 u = *(const uint4*)p;
    const __half2* hp = (const __half2*)&u;
#pragma unroll
    for (int i = 0; i < 4; i++) {
        float2 t = __half22float2(hp[i]);
        f[2 * i] = t.x; f[2 * i + 1] = t.y;
    }
}

// ---------------- fused: init deg + dtype detect ----------------
__global__ void k_detect_init(const void* edge, int gN) {
    if (blockIdx.x < gN) {
        int i = blockIdx.x * blockDim.x + threadIdx.x;
        if (i < N_NODES) g_deg[i] = 1;
        return;
    }
    __shared__ int any;
    if (threadIdx.x == 0) any = 0;
    __syncthreads();
    const int* w = (const int*)edge;
    int local = 0;
    for (int i = threadIdx.x; i < 1024; i += blockDim.x)
        if (w[2 * i + 1] != 0) local = 1;
    if (local) atomicOr(&any, 1);
    __syncthreads();
    if (threadIdx.x == 0) g_is64 = (any == 0) ? 1 : 0;
}

__global__ void k_count(const void* edge) {
    int e = blockIdx.x * blockDim.x + threadIdx.x;
    if (e >= N_EDGES) return;
    int is64 = g_is64;
    int d = load_idx(edge, (long long)N_EDGES + e, is64);
    atomicAdd(&g_deg[d], 1);
}

// ---------------- parallel 3-pass scan ----------------
__global__ void __launch_bounds__(1024) k_scan1() {
    __shared__ int wsum[32];
    int b    = blockIdx.x;
    int tid  = threadIdx.x;
    int lane = tid & 31;
    int wid  = tid >> 5;

    int i0 = b * SCAN_CH + tid * 2;
    int d0 = (i0     < N_NODES) ? g_deg[i0]     : 1;
    int d1 = (i0 + 1 < N_NODES) ? g_deg[i0 + 1] : 1;
    int v0 = (i0     < N_NODES) ? (d0 - 1) : 0;
    int v1 = (i0 + 1 < N_NODES) ? (d1 - 1) : 0;
    int v = v0 + v1;

    int x = v;
#pragma unroll
    for (int off = 1; off < 32; off <<= 1) {
        int t = __shfl_up_sync(0xffffffff, x, off);
        if (lane >= off) x += t;
    }
    if (lane == 31) wsum[wid] = x;
    __syncthreads();
    if (wid == 0) {
        int y = wsum[lane];
#pragma unroll
        for (int off = 1; off < 32; off <<= 1) {
            int t = __shfl_up_sync(0xffffffff, y, off);
            if (lane >= off) y += t;
        }
        wsum[lane] = y;
    }
    __syncthreads();

    int base = (wid ? wsum[wid - 1] : 0) + x - v;
    if (i0 < N_NODES) {
        g_rowptr[i0] = base;
        g_dinv[i0]   = rsqrtf((float)d0);
    }
    if (i0 + 1 < N_NODES) {
        g_rowptr[i0 + 1] = base + v0;
        g_dinv[i0 + 1]   = rsqrtf((float)d1);
    }
    if (tid == 0) g_bsum[b] = 0;
    __syncthreads();
    if (tid == 1023) g_bsum[b] = wsum[31];
}

__global__ void k_scan2() {
    int lane = threadIdx.x;
    int v = (lane < SCAN_NBLK) ? g_bsum[lane] : 0;
    int x = v;
#pragma unroll
    for (int off = 1; off < 32; off <<= 1) {
        int t = __shfl_up_sync(0xffffffff, x, off);
        if (lane >= off) x += t;
    }
    if (lane < SCAN_NBLK) g_boff[lane] = x - v;
    if (lane == 31) g_rowptr[N_NODES] = x;
}

__global__ void k_scan3() {
    int i = blockIdx.x * blockDim.x + threadIdx.x;
    if (i >= N_NODES) return;
    int off = g_boff[i / SCAN_CH];
    int r = g_rowptr[i] + off;
    g_rowptr[i] = r;
    g_cursor[i] = r;
}

__global__ void k_scatter(const void* edge) {
    int e = blockIdx.x * blockDim.x + threadIdx.x;
    if (e >= N_EDGES) return;
    int is64 = g_is64;
    int srce = load_idx(edge, e, is64);
    int dste = load_idx(edge, (long long)N_EDGES + e, is64);
    int pos = atomicAdd(&g_cursor[dste], 1);
    g_csr_src[pos] = srce;
}

// ---------------- tf32 tensor-core GEMM: C[M,256](fp16) = A @ W ----------
#define BM 128
#define BN 128
#define BK 16
#define ASTRIDE (BM + 8)
#define BSTRIDE (BN + 8)

__device__ __forceinline__ void mma_tf32(float* c, const uint32_t* a, const uint32_t* b) {
    asm volatile(
        "mma.sync.aligned.m16n8k8.row.col.f32.tf32.tf32.f32 "
        "{%0,%1,%2,%3}, {%4,%5,%6,%7}, {%8,%9}, {%0,%1,%2,%3};"
        : "+f"(c[0]), "+f"(c[1]), "+f"(c[2]), "+f"(c[3])
        : "r"(a[0]), "r"(a[1]), "r"(a[2]), "r"(a[3]), "r"(b[0]), "r"(b[1]));
}

__device__ __forceinline__ float4 loadA4(const float* A, size_t off) {
    return *(const float4*)(A + off);
}
__device__ __forceinline__ float4 loadA4(const __half* A, size_t off) {
    uint2 u = *(const uint2*)(A + off);
    float2 f0 = __half22float2(*reinterpret_cast<__half2*>(&u.x));
    float2 f1 = __half22float2(*reinterpret_cast<__half2*>(&u.y));
    return make_float4(f0.x, f0.y, f1.x, f1.y);
}

template <typename AT>
__global__ void __launch_bounds__(256)
k_gemm(const AT* __restrict__ A, const float* __restrict__ W,
       __half* __restrict__ C, int M) {
    __shared__ float As[2][BK][ASTRIDE];
    __shared__ float Bs[2][BK][BSTRIDE];

    int tid = threadIdx.x;
    int lane = tid & 31;
    int wid  = tid >> 5;
    int gid  = lane >> 2;
    int tig  = lane & 3;
    int wm = (wid & 1) * 64;
    int wn = (wid >> 1) * 32;
    int m0 = blockIdx.x * BM;
    int n0 = blockIdx.y * BN;

    int arow0 = tid >> 2;
    int ac4   = tid & 3;
    int brow0 = tid >> 5;
    int bc4   = tid & 31;

    float acc[4][4][4];
#pragma unroll
    for (int i = 0; i < 4; i++)
#pragma unroll
        for (int j = 0; j < 4; j++)
#pragma unroll
            for (int r = 0; r < 4; r++) acc[i][j][r] = 0.f;

    float4 pa0, pa1, pb0, pb1;
    {
        int m = m0 + arow0;
        pa0 = (m < M) ? loadA4(A, (size_t)m * 256 + ac4 * 4)
                      : make_float4(0.f, 0.f, 0.f, 0.f);
        m = m0 + arow0 + 64;
        pa1 = (m < M) ? loadA4(A, (size_t)m * 256 + ac4 * 4)
                      : make_float4(0.f, 0.f, 0.f, 0.f);
        pb0 = *(const float4*)&W[(size_t)brow0 * 256 + n0 + bc4 * 4];
        pb1 = *(const float4*)&W[(size_t)(brow0 + 8) * 256 + n0 + bc4 * 4];
    }
    {
        As[0][ac4 * 4 + 0][arow0] = __uint_as_float(to_tf32(pa0.x));
        As[0][ac4 * 4 + 1][arow0] = __uint_as_float(to_tf32(pa0.y));
        As[0][ac4 * 4 + 2][arow0] = __uint_as_float(to_tf32(pa0.z));
        As[0][ac4 * 4 + 3][arow0] = __uint_as_float(to_tf32(pa0.w));
        As[0][ac4 * 4 + 0][arow0 + 64] = __uint_as_float(to_tf32(pa1.x));
        As[0][ac4 * 4 + 1][arow0 + 64] = __uint_as_float(to_tf32(pa1.y));
        As[0][ac4 * 4 + 2][arow0 + 64] = __uint_as_float(to_tf32(pa1.z));
        As[0][ac4 * 4 + 3][arow0 + 64] = __uint_as_float(to_tf32(pa1.w));
        float4 q0 = make_float4(__uint_as_float(to_tf32(pb0.x)), __uint_as_float(to_tf32(pb0.y)),
                                __uint_as_float(to_tf32(pb0.z)), __uint_as_float(to_tf32(pb0.w)));
        float4 q1 = make_float4(__uint_as_float(to_tf32(pb1.x)), __uint_as_float(to_tf32(pb1.y)),
                                __uint_as_float(to_tf32(pb1.z)), __uint_as_float(to_tf32(pb1.w)));
        *(float4*)&Bs[0][brow0][bc4 * 4]     = q0;
        *(float4*)&Bs[0][brow0 + 8][bc4 * 4] = q1;
    }
    __syncthreads();

    int buf = 0;
    for (int k0 = 0; k0 < 256; k0 += BK) {
        bool has_next = (k0 + BK) < 256;
        if (has_next) {
            int kb = k0 + BK;
            int m = m0 + arow0;
            pa0 = (m < M) ? loadA4(A, (size_t)m * 256 + kb + ac4 * 4)
                          : make_float4(0.f, 0.f, 0.f, 0.f);
            m = m0 + arow0 + 64;
            pa1 = (m < M) ? loadA4(A, (size_t)m * 256 + kb + ac4 * 4)
                          : make_float4(0.f, 0.f, 0.f, 0.f);
            pb0 = *(const float4*)&W[(size_t)(kb + brow0) * 256 + n0 + bc4 * 4];
            pb1 = *(const float4*)&W[(size_t)(kb + brow0 + 8) * 256 + n0 + bc4 * 4];
        }

#pragma unroll
        for (int ks = 0; ks < 2; ks++) {
            int kb = ks * 8;
            uint32_t af[4][4];
            uint32_t bf[4][2];
#pragma unroll
            for (int mt = 0; mt < 4; mt++) {
                int m = wm + mt * 16 + gid;
                af[mt][0] = __float_as_uint(As[buf][kb + tig][m]);
                af[mt][1] = __float_as_uint(As[buf][kb + tig][m + 8]);
                af[mt][2] = __float_as_uint(As[buf][kb + tig + 4][m]);
                af[mt][3] = __float_as_uint(As[buf][kb + tig + 4][m + 8]);
            }
#pragma unroll
            for (int nt = 0; nt < 4; nt++) {
                int nn = wn + nt * 8 + gid;
                bf[nt][0] = __float_as_uint(Bs[buf][kb + tig][nn]);
                bf[nt][1] = __float_as_uint(Bs[buf][kb + tig + 4][nn]);
            }
#pragma unroll
            for (int mt = 0; mt < 4; mt++)
#pragma unroll
                for (int nt = 0; nt < 4; nt++)
                    mma_tf32(acc[mt][nt], af[mt], bf[nt]);
        }

        if (has_next) {
            int nb = buf ^ 1;
            As[nb][ac4 * 4 + 0][arow0] = __uint_as_float(to_tf32(pa0.x));
            As[nb][ac4 * 4 + 1][arow0] = __uint_as_float(to_tf32(pa0.y));
            As[nb][ac4 * 4 + 2][arow0] = __uint_as_float(to_tf32(pa0.z));
            As[nb][ac4 * 4 + 3][arow0] = __uint_as_float(to_tf32(pa0.w));
            As[nb][ac4 * 4 + 0][arow0 + 64] = __uint_as_float(to_tf32(pa1.x));
            As[nb][ac4 * 4 + 1][arow0 + 64] = __uint_as_float(to_tf32(pa1.y));
            As[nb][ac4 * 4 + 2][arow0 + 64] = __uint_as_float(to_tf32(pa1.z));
            As[nb][ac4 * 4 + 3][arow0 + 64] = __uint_as_float(to_tf32(pa1.w));
            float4 q0 = make_float4(__uint_as_float(to_tf32(pb0.x)), __uint_as_float(to_tf32(pb0.y)),
                                    __uint_as_float(to_tf32(pb0.z)), __uint_as_float(to_tf32(pb0.w)));
            float4 q1 = make_float4(__uint_as_float(to_tf32(pb1.x)), __uint_as_float(to_tf32(pb1.y)),
                                    __uint_as_float(to_tf32(pb1.z)), __uint_as_float(to_tf32(pb1.w)));
            *(float4*)&Bs[nb][brow0][bc4 * 4]     = q0;
            *(float4*)&Bs[nb][brow0 + 8][bc4 * 4] = q1;
            __syncthreads();
            buf = nb;
        }
    }

    // epilogue: fp16 stores
#pragma unroll
    for (int mt = 0; mt < 4; mt++) {
#pragma unroll
        for (int nt = 0; nt < 4; nt++) {
            int r0 = m0 + wm + mt * 16 + gid;
            int col = n0 + wn + nt * 8 + tig * 2;
            if (r0 < M)
                *(__half2*)&C[(size_t)r0 * 256 + col] =
                    __floats2half2_rn(acc[mt][nt][0], acc[mt][nt][1]);
            if (r0 + 8 < M)
                *(__half2*)&C[(size_t)(r0 + 8) * 256 + col] =
                    __floats2half2_rn(acc[mt][nt][2], acc[mt][nt][3]);
        }
    }
}

// ---------------- fused aggregate + bias + LayerNorm + LeakyReLU ----------
// h in fp16; out is fp16 (layer1) or fp32 (layer2). One warp per node.
template <typename OutT>
__global__ void k_agg_ln(const __half* __restrict__ h, OutT* __restrict__ out,
                         const float* __restrict__ bias,
                         const float* __restrict__ lnw,
                         const float* __restrict__ lnb) {
    int warp = (blockIdx.x * blockDim.x + threadIdx.x) >> 5;
    int lane = threadIdx.x & 31;
    if (warp >= N_NODES) return;
    int node = warp;
    int f0 = lane * 8;   // first feature owned by lane

    float di = g_dinv[node];
    float ws = di * di;

    float acc[4][8];
    {
        float sf[8];
        load8h(h + (size_t)node * HID + f0, sf);
#pragma unroll
        for (int i = 0; i < 8; i++) acc[0][i] = sf[i] * ws;
#pragma unroll
        for (int u = 1; u < 4; u++)
#pragma unroll
            for (int i = 0; i < 8; i++) acc[u][i] = 0.f;
    }

    int beg = g_rowptr[node];
    int end = g_rowptr[node + 1];
    int e = beg;
    for (; e + 3 < end; e += 4) {
        int s0 = g_csr_src[e];
        int s1 = g_csr_src[e + 1];
        int s2 = g_csr_src[e + 2];
        int s3 = g_csr_src[e + 3];
        float w0 = g_dinv[s0] * di;
        float w1 = g_dinv[s1] * di;
        float w2 = g_dinv[s2] * di;
        float w3 = g_dinv[s3] * di;
        float r0[8], r1[8], r2[8], r3[8];
        load8h(h + (size_t)s0 * HID + f0, r0);
        load8h(h + (size_t)s1 * HID + f0, r1);
        load8h(h + (size_t)s2 * HID + f0, r2);
        load8h(h + (size_t)s3 * HID + f0, r3);
#pragma unroll
        for (int i = 0; i < 8; i++) {
            acc[0][i] += r0[i] * w0;
            acc[1][i] += r1[i] * w1;
            acc[2][i] += r2[i] * w2;
            acc[3][i] += r3[i] * w3;
        }
    }
    for (; e < end; e++) {
        int s = g_csr_src[e];
        float wv = g_dinv[s] * di;
        float r[8];
        load8h(h + (size_t)s * HID + f0, r);
#pragma unroll
        for (int i = 0; i < 8; i++) acc[0][i] += r[i] * wv;
    }

    float a[8];
#pragma unroll
    for (int i = 0; i < 8; i++)
        a[i] = (acc[0][i] + acc[1][i]) + (acc[2][i] + acc[3][i]);

    // + bias
    float4 b0 = ((const float4*)bias)[lane * 2];
    float4 b1 = ((const float4*)bias)[lane * 2 + 1];
    a[0] += b0.x; a[1] += b0.y; a[2] += b0.z; a[3] += b0.w;
    a[4] += b1.x; a[5] += b1.y; a[6] += b1.z; a[7] += b1.w;

    // LayerNorm
    float sum = 0.f;
#pragma unroll
    for (int i = 0; i < 8; i++) sum += a[i];
#pragma unroll
    for (int off = 16; off > 0; off >>= 1)
        sum += __shfl_xor_sync(0xffffffff, sum, off);
    float mu = sum * (1.0f / HID);

    float d[8], sq = 0.f;
#pragma unroll
    for (int i = 0; i < 8; i++) { d[i] = a[i] - mu; sq += d[i] * d[i]; }
#pragma unroll
    for (int off = 16; off > 0; off >>= 1)
        sq += __shfl_xor_sync(0xffffffff, sq, off);
    float inv = rsqrtf(sq * (1.0f / HID) + LN_EPS);

    float4 w0 = ((const float4*)lnw)[lane * 2];
    float4 w1 = ((const float4*)lnw)[lane * 2 + 1];
    float4 lb0 = ((const float4*)lnb)[lane * 2];
    float4 lb1 = ((const float4*)lnb)[lane * 2 + 1];
    float lw[8] = {w0.x, w0.y, w0.z, w0.w, w1.x, w1.y, w1.z, w1.w};
    float lb[8] = {lb0.x, lb0.y, lb0.z, lb0.w, lb1.x, lb1.y, lb1.z, lb1.w};

    float v[8];
#pragma unroll
    for (int i = 0; i < 8; i++) {
        float t = d[i] * inv * lw[i] + lb[i];
        v[i] = (t >= 0.f) ? t : LEAKY * t;
    }

    if constexpr (sizeof(OutT) == 2) {
        __half2 o[4];
#pragma unroll
        for (int i = 0; i < 4; i++) o[i] = __floats2half2_rn(v[2 * i], v[2 * i + 1]);
        *(uint4*)((__half*)out + (size_t)node * HID + f0) = *(uint4*)o;
    } else {
        float* orow = (float*)out + (size_t)node * HID + f0;
        *(float4*)&orow[0] = make_float4(v[0], v[1], v[2], v[3]);
        *(float4*)&orow[4] = make_float4(v[4], v[5], v[6], v[7]);
    }
}

// ---------------- per-graph mean pool (fp32 input) ----------------
__global__ void k_pool(const float* __restrict__ h, const void* batch,
                       float* __restrict__ out) {
    int g = blockIdx.x;
    int is64 = g_is64;

    int lo = 0, hi = N_NODES;
    while (lo < hi) {
        int mid = (lo + hi) >> 1;
        if (load_idx(batch, mid, is64) < g) lo = mid + 1; else hi = mid;
    }
    int start = lo;
    hi = N_NODES;
    while (lo < hi) {
        int mid = (lo + hi) >> 1;
        if (load_idx(batch, mid, is64) < g + 1) lo = mid + 1; else hi = mid;
    }
    int end = lo;

    int t = threadIdx.x;
    float a0 = 0.f, a1 = 0.f, a2 = 0.f, a3 = 0.f;
    int i = start;
    for (; i + 3 < end; i += 4) {
        a0 += h[(size_t)(i + 0) * HID + t];
        a1 += h[(size_t)(i + 1) * HID + t];
        a2 += h[(size_t)(i + 2) * HID + t];
        a3 += h[(size_t)(i + 3) * HID + t];
    }
    for (; i < end; i++) a0 += h[(size_t)i * HID + t];
    float acc = (a0 + a1) + (a2 + a3);
    float cnt = (float)(end - start);
    out[(size_t)g * HID + t] = acc / fmaxf(cnt, 1.f);
}

// ---------------- launch ----------------
extern "C" void kernel_launch(void* const* d_in, const int* in_sizes, int n_in,
                              void* d_out, int out_size) {
    const float* x    = (const float*)d_in[0];
    const void*  edge = d_in[1];
    const void*  batch= d_in[2];
    const float* W1   = (const float*)d_in[3];
    const float* b1   = (const float*)d_in[4];
    const float* ln1w = (const float*)d_in[5];
    const float* ln1b = (const float*)d_in[6];
    const float* W2   = (const float*)d_in[7];
    const float* b2   = (const float*)d_in[8];
    const float* ln2w = (const float*)d_in[9];
    const float* ln2b = (const float*)d_in[10];
    float* out = (float*)d_out;

    __half *hA = nullptr, *hB = nullptr;
    float  *hC = nullptr;
    cudaGetSymbolAddress((void**)&hA, g_h16A);
    cudaGetSymbolAddress((void**)&hB, g_h16B);
    cudaGetSymbolAddress((void**)&hC, g_hC);

    static cudaStream_t s_side = nullptr;
    static cudaEvent_t  s_fork = nullptr, s_join = nullptr;
    static int s_ok = -1;
    if (s_ok < 0) {
        s_ok = 1;
        if (cudaStreamCreateWithFlags(&s_side, cudaStreamNonBlocking) != cudaSuccess) s_ok = 0;
        if (s_ok && cudaEventCreateWithFlags(&s_fork, cudaEventDisableTiming) != cudaSuccess) s_ok = 0;
        if (s_ok && cudaEventCreateWithFlags(&s_join, cudaEventDisableTiming) != cudaSuccess) s_ok = 0;
    }
    cudaStream_t side = s_ok ? s_side : (cudaStream_t)0;

    const int TB = 256;
    int gN = (N_NODES + TB - 1) / TB;
    int gE = (N_EDGES + TB - 1) / TB;

    dim3 gemmGrid((N_NODES + BM - 1) / BM, 256 / BN);
    int aggBlocks = (N_NODES * 32 + TB - 1) / TB;

    if (s_ok) {
        cudaEventRecord(s_fork, 0);
        cudaStreamWaitEvent(side, s_fork, 0);
    }

    k_gemm<float><<<gemmGrid, TB>>>(x, W1, hA, N_NODES);     // main stream

    k_detect_init<<<gN + 1, TB, 0, side>>>(edge, gN);        // side stream
    k_count<<<gE, TB, 0, side>>>(edge);
    k_scan1<<<SCAN_NBLK, 1024, 0, side>>>();
    k_scan2<<<1, 32, 0, side>>>();
    k_scan3<<<gN, TB, 0, side>>>();
    k_scatter<<<gE, TB, 0, side>>>(edge);

    if (s_ok) {
        cudaEventRecord(s_join, side);
        cudaStreamWaitEvent(0, s_join, 0);
    }

    k_agg_ln<__half><<<aggBlocks, TB>>>(hA, hB, b1, ln1w, ln1b);

    k_gemm<__half><<<gemmGrid, TB>>>(hB, W2, hA, N_NODES);
    k_agg_ln<float><<<aggBlocks, TB>>>(hA, hC, b2, ln2w, ln2b);

    k_pool<<<NUM_GRAPHS, HID>>>(hC, batch, out);
}